// round 16
// baseline (speedup 1.0000x reference)
#include <cuda_runtime.h>
#include <cuda.h>
#include <cuda_bf16.h>
#include <cstdint>

#define B_ 8
#define C_ 512
#define T_ 1024
#define H_ 8
#define D_ 64
#define REL_ 129

#if defined(__CUDA_ARCH_FEAT_SM103_ALL) || defined(__CUDA_ARCH_FEAT_SM100_ALL) || defined(__CUDA_ARCH_FEAT_SM101_ALL)
#define HAS_TCGEN05 1
#else
#define HAS_TCGEN05 0
#endif

// ---------------- scratch (no cudaMalloc allowed) ----------------
__device__ __nv_bfloat16 g_xthi[B_*T_*C_];
__device__ __nv_bfloat16 g_xtlo[B_*T_*C_];
__device__ __nv_bfloat16 g_whi[4*C_*C_];
__device__ __nv_bfloat16 g_wlo[4*C_*C_];
__device__ __nv_bfloat16 g_qhi[B_*H_*T_*D_];
__device__ __nv_bfloat16 g_qlo[B_*H_*T_*D_];
__device__ __nv_bfloat16 g_khi[B_*H_*T_*D_];
__device__ __nv_bfloat16 g_klo[B_*H_*T_*D_];
__device__ __nv_bfloat16 g_vhi[B_*H_*T_*D_];   // (B,H,D,T)
__device__ __nv_bfloat16 g_vlo[B_*H_*T_*D_];
__device__ __nv_bfloat16 g_ythi[B_*T_*C_];
__device__ __nv_bfloat16 g_ytlo[B_*T_*C_];
__device__ __nv_bfloat16 g_ekhi[REL_*D_];
__device__ __nv_bfloat16 g_eklo[REL_*D_];
__device__ __nv_bfloat16 g_evhi[D_*144];
__device__ __nv_bfloat16 g_evlo[D_*144];

// ---------------- attn shared memory ----------------
#define OFF_QHI   0
#define OFF_QLO   9216
#define OFF_K     18432
#define OFF_V     55296
#define OFF_P     90112
#define OFF_SBIN  124928      // binhi bf16 [64][144]
#define OFF_SQR   158720
#define OFF_SMK   193536
#define OFF_SSTP  197632
#define OFF_SST   200704
#define OFF_BINLO2 201472     // binlo bf16 [64][144]
#define SMEM_BYTES 219904
#define OFF_EKHI  18432
#define OFF_EKLO  39168
#define OFF_EVHI  57344
#define OFF_EVLO  76800

// ---------------- proj (2-stage TMA, N=128) ----------------
#define PJ2_SMEM 132096
#define PT_TMEM 0
#define PT_MB0  8      // full stage0
#define PT_MB1  16     // full stage1
#define PT_MB2  24     // done stage0
#define PT_MB3  32     // done stage1
#define PT_STAGE0 1024
#define PT_STAGE1 (1024+65536)
// ---------------- outp (1-stage, N=256) ----------------
#define PO_SMEM 99840
#define PT_AH   1024
#define PT_AL   17408
#define PT_BH   33792
#define PT_BL   66560
#define IDESC_P 0x8100490u   // kind::f16: F32 acc, BF16xBF16, M=128, N=64

// ---------------- helpers ----------------
__device__ __forceinline__ unsigned pk2(__nv_bfloat16 a, __nv_bfloat16 b) {
    __nv_bfloat162 t = __halves2bfloat162(a, b);
    return *reinterpret_cast<unsigned*>(&t);
}
__device__ __forceinline__ void cv(float x, __nv_bfloat16& h, __nv_bfloat16& l) {
    h = __float2bfloat16(x);
    l = __float2bfloat16(x - __bfloat162float(h));
}
__device__ __forceinline__ void cv2(float v0, float v1, unsigned& hi2, unsigned& lo2) {
    asm("cvt.rn.bf16x2.f32 %0, %1, %2;" : "=r"(hi2) : "f"(v1), "f"(v0));
    float h0 = __uint_as_float(hi2 << 16);
    float h1 = __uint_as_float(hi2 & 0xFFFF0000u);
    float l0 = v0 - h0, l1 = v1 - h1;
    asm("cvt.rn.bf16x2.f32 %0, %1, %2;" : "=r"(lo2) : "f"(l1), "f"(l0));
}
__device__ __forceinline__ unsigned su32(const void* p) {
    return (unsigned)__cvta_generic_to_shared(p);
}
__device__ __forceinline__ void cpasync16(unsigned s, const void* g) {
    asm volatile("cp.async.cg.shared.global [%0], [%1], 16;" :: "r"(s), "l"(g));
}
__device__ __forceinline__ void cp_commit() {
    asm volatile("cp.async.commit_group;" ::: "memory");
}
__device__ __forceinline__ void cp_wait0() {
    asm volatile("cp.async.wait_group 0;" ::: "memory");
}
__device__ __forceinline__ void cp_wait1() {
    asm volatile("cp.async.wait_group 1;" ::: "memory");
}
__device__ __forceinline__ void ldsm4(unsigned& r0, unsigned& r1, unsigned& r2,
                                      unsigned& r3, unsigned addr) {
    asm volatile("ldmatrix.sync.aligned.m8n8.x4.shared.b16 {%0,%1,%2,%3}, [%4];"
                 : "=r"(r0), "=r"(r1), "=r"(r2), "=r"(r3) : "r"(addr));
}
__device__ __forceinline__ void mma16816(float* c, unsigned a0, unsigned a1,
                                         unsigned a2, unsigned a3,
                                         unsigned b0, unsigned b1) {
    asm volatile(
        "mma.sync.aligned.m16n8k16.row.col.f32.bf16.bf16.f32 "
        "{%0,%1,%2,%3}, {%4,%5,%6,%7}, {%8,%9}, {%0,%1,%2,%3};"
        : "+f"(c[0]), "+f"(c[1]), "+f"(c[2]), "+f"(c[3])
        : "r"(a0), "r"(a1), "r"(a2), "r"(a3), "r"(b0), "r"(b1));
}

#if HAS_TCGEN05
__device__ __forceinline__ uint32_t elect_one_pred() {
    uint32_t pred;
    asm volatile(
        "{\n\t.reg .pred p;\n\t"
        "elect.sync _|p, 0xFFFFFFFF;\n\t"
        "selp.b32 %0, 1, 0, p;\n\t}"
        : "=r"(pred));
    return pred;
}
static constexpr uint64_t SMEM_DESC_BASE_SW128 =
    (uint64_t(2)  << 61) | (uint64_t(1) << 46) | (uint64_t(64) << 32) | (uint64_t(1) << 16);
#define MAKE_SMEM_DESC(base_addr) \
    (SMEM_DESC_BASE_SW128 | ((uint64_t)((base_addr) >> 4) & 0x3FFF))
#define TCGEN05_ALLOC(smem_result_addr, nCols) \
    asm volatile("tcgen05.alloc.cta_group::1.sync.aligned.shared::cta.b32 [%0], %1;" \
        :: "r"((uint32_t)(smem_result_addr)), "r"((uint32_t)(nCols)) : "memory")
#define TCGEN05_DEALLOC(tmem_addr, nCols) \
    asm volatile("tcgen05.dealloc.cta_group::1.sync.aligned.b32 %0, %1;" \
        :: "r"(tmem_addr), "r"((uint32_t)(nCols)))
#define TCGEN05_COMMIT(mbar_smem_addr) \
    asm volatile("tcgen05.commit.cta_group::1.mbarrier::arrive::one.shared::cluster.b64 [%0];" \
        :: "r"((uint32_t)(mbar_smem_addr)) : "memory")
#define TCGEN05_FENCE_BEFORE() \
    asm volatile("tcgen05.fence::before_thread_sync;" ::: "memory")
#define TCGEN05_FENCE_AFTER() \
    asm volatile("tcgen05.fence::after_thread_sync;" ::: "memory")
#define TCGEN05_WAIT_LD() \
    asm volatile("tcgen05.wait::ld.sync.aligned;" ::: "memory")
#define FENCE_PROXY_ASYNC_SHARED_CTA() \
    asm volatile("fence.proxy.async.shared::cta;" ::: "memory")
#define TCGEN05_LD_32X32B_X32(r, tmem_addr) \
    asm volatile( \
        "tcgen05.ld.sync.aligned.32x32b.x32.b32 " \
        "{%0, %1, %2, %3, %4, %5, %6, %7, " \
        " %8, %9, %10, %11, %12, %13, %14, %15, " \
        " %16, %17, %18, %19, %20, %21, %22, %23, " \
        " %24, %25, %26, %27, %28, %29, %30, %31}, [%32];" \
        : "=r"((r)[0]),  "=r"((r)[1]),  "=r"((r)[2]),  "=r"((r)[3]), \
          "=r"((r)[4]),  "=r"((r)[5]),  "=r"((r)[6]),  "=r"((r)[7]), \
          "=r"((r)[8]),  "=r"((r)[9]),  "=r"((r)[10]), "=r"((r)[11]), \
          "=r"((r)[12]), "=r"((r)[13]), "=r"((r)[14]), "=r"((r)[15]), \
          "=r"((r)[16]), "=r"((r)[17]), "=r"((r)[18]), "=r"((r)[19]), \
          "=r"((r)[20]), "=r"((r)[21]), "=r"((r)[22]), "=r"((r)[23]), \
          "=r"((r)[24]), "=r"((r)[25]), "=r"((r)[26]), "=r"((r)[27]), \
          "=r"((r)[28]), "=r"((r)[29]), "=r"((r)[30]), "=r"((r)[31]) \
        : "r"(tmem_addr))
__device__ __forceinline__ void tcg_f16_ss(uint32_t d_tmem, uint64_t a_desc,
                                           uint64_t b_desc, uint32_t idesc, bool acc)
{
    uint32_t en = acc ? 1u : 0u;
    asm volatile(
        "{\n\t.reg .pred p;\n\t"
        "setp.ne.u32 p, %5, 0;\n\t"
        "tcgen05.mma.cta_group::1.kind::f16 [%0], %1, %2, %3, {%4,%4,%4,%4}, p;\n\t}"
        :: "r"(d_tmem), "l"(a_desc), "l"(b_desc), "r"(idesc), "r"(0u), "r"(en)
        : "memory");
}
#define MBARRIER_EXPECT_TX(mbar_smem_addr, tx_bytes) \
    asm volatile("mbarrier.arrive.expect_tx.shared.b64 _, [%0], %1;" \
        :: "r"((uint32_t)(mbar_smem_addr)), "r"((uint32_t)(tx_bytes)) : "memory")
#define TMA2D(smem_addr, mapref, x, y, mbar) \
    asm volatile( \
        "cp.async.bulk.tensor.2d.shared::cta.global.tile.mbarrier::complete_tx::bytes " \
        "[%0], [%1, {%2, %3}], [%4];" \
        :: "r"((uint32_t)(smem_addr)), "l"(&(mapref)), "r"((int)(x)), "r"((int)(y)), \
           "r"((uint32_t)(mbar)) : "memory")
#endif // HAS_TCGEN05

#define MBARRIER_INIT(mbar_smem_addr, count) \
    asm volatile("mbarrier.init.shared.b64 [%0], %1;" \
        :: "r"((uint32_t)(mbar_smem_addr)), "r"((uint32_t)(count)) : "memory")
#define MBARRIER_WAIT_PARITY(mbar_smem_addr, phase_parity) do { \
    uint32_t _mbar = (uint32_t)(mbar_smem_addr); \
    uint32_t _parity = (uint32_t)(phase_parity); \
    uint32_t _done; \
    asm volatile( \
        "{\n\t.reg .pred p;\n\t" \
        "mbarrier.try_wait.parity.acquire.cta.shared::cta.b64 p, [%1], %2;\n\t" \
        "selp.b32 %0, 1, 0, p;\n\t}" \
        : "=r"(_done) : "r"(_mbar), "r"(_parity) : "memory"); \
    if (!_done) { \
        asm volatile( \
            "{\n\t.reg .pred P1;\n\t" \
            "WAIT_LOOP_%=:\n\t" \
            "mbarrier.try_wait.parity.acquire.cta.shared::cta.b64 P1, [%0], %1, 0x989680;\n\t" \
            "@P1 bra.uni WAIT_DONE_%=;\n\t" \
            "bra.uni WAIT_LOOP_%=;\n\t" \
            "WAIT_DONE_%=:\n\t}" \
            :: "r"(_mbar), "r"(_parity) : "memory"); \
    } \
} while(0)

// =====================================================================
// prep kernels (unchanged)
// =====================================================================
__global__ __launch_bounds__(256) void conv_x(const float* __restrict__ x)
{
    __shared__ float s[32][33];
    const int b = blockIdx.z, c0 = blockIdx.y*32, t0 = blockIdx.x*32;
    const int tx = threadIdx.x & 31, ty = threadIdx.x >> 5;
    #pragma unroll
    for (int r = 0; r < 4; r++) {
        int c = ty + r*8;
        s[c][tx] = x[((size_t)b*C_ + c0 + c)*T_ + t0 + tx];
    }
    __syncthreads();
    #pragma unroll
    for (int r = 0; r < 4; r++) {
        int t = ty + r*8;
        float v = s[tx][t];
        __nv_bfloat16 h, l;
        cv(v, h, l);
        size_t idx = ((size_t)b*T_ + t0 + t)*C_ + c0 + tx;
        g_xthi[idx] = h;
        g_xtlo[idx] = l;
    }
}

__global__ __launch_bounds__(256) void conv_w(
    const float* __restrict__ w0, const float* __restrict__ w1,
    const float* __restrict__ w2, const float* __restrict__ w3)
{
    const int g = blockIdx.y;
    const float* W = g==0 ? w0 : g==1 ? w1 : g==2 ? w2 : w3;
    int idx = blockIdx.x*256 + threadIdx.x;
    float v = W[idx];
    __nv_bfloat16 h, l;
    cv(v, h, l);
    g_whi[(size_t)g*C_*C_ + idx] = h;
    g_wlo[(size_t)g*C_*C_ + idx] = l;
}

__global__ __launch_bounds__(256) void conv_erel(
    const float* __restrict__ erelk, const float* __restrict__ erelv)
{
    int idx = blockIdx.x*256 + threadIdx.x;
    if (idx < REL_*D_) {
        __nv_bfloat16 h, l;
        cv(erelk[idx], h, l);
        g_ekhi[idx] = h; g_eklo[idx] = l;
    }
    if (idx < D_*144) {
        int d = idx / 144, r = idx - d*144;
        float v = (r < REL_) ? erelv[r*D_ + d] : 0.f;
        __nv_bfloat16 h, l;
        cv(v, h, l);
        g_evhi[idx] = h; g_evlo[idx] = l;
    }
}

// =====================================================================
// QKV projection — tcgen05 + TMA staging (2-stage) / mma.sync fallback
// =====================================================================
__global__ __launch_bounds__(256) void proj_any(
    const __grid_constant__ CUtensorMap mXh,
    const __grid_constant__ CUtensorMap mXl,
    const __grid_constant__ CUtensorMap mWh,
    const __grid_constant__ CUtensorMap mWl,
    const float* __restrict__ bq, const float* __restrict__ bk,
    const float* __restrict__ bv)
{
    extern __shared__ unsigned char smem[];
    const int tid = threadIdx.x, lane = tid & 31, w = tid >> 5;

    const int ny = blockIdx.y;
    const int wsel = ny >> 2;
    const int o0 = (ny & 3) * 128;
    const int m0g = blockIdx.x * 128;
    const int b = m0g >> 10, t0 = m0g & 1023;

    const float* bias = wsel==0 ? bq : (wsel==1 ? bk : bv);

#if HAS_TCGEN05
    const uint32_t sb = su32(smem);
    if (w == 0) TCGEN05_ALLOC(sb + PT_TMEM, 128);
    if (tid == 0) {
        MBARRIER_INIT(sb + PT_MB0, 1);
        MBARRIER_INIT(sb + PT_MB1, 1);
        MBARRIER_INIT(sb + PT_MB2, 1);
        MBARRIER_INIT(sb + PT_MB3, 1);
    }
    __syncthreads();
    uint32_t tmem;
    asm volatile("ld.shared.b32 %0, [%1];" : "=r"(tmem) : "r"(sb + PT_TMEM));

    if (w == 0) {
        const uint32_t stg[2] = { sb + PT_STAGE0, sb + PT_STAGE1 };
        const uint32_t mbF[2] = { sb + PT_MB0, sb + PT_MB1 };
        const uint32_t mbD[2] = { sb + PT_MB2, sb + PT_MB3 };
        const int wrow = wsel*512 + o0;
        const uint32_t el = elect_one_pred();

        // issue 4 TMA loads for chunk kt into stage s
        #define PTMA(ktv, s) do { \
            if (el) { \
                const int kx = (ktv) * 64; \
                MBARRIER_EXPECT_TX(mbF[s], 65536u); \
                TMA2D(stg[s],         mXh, kx, m0g,  mbF[s]); \
                TMA2D(stg[s] + 16384, mXl, kx, m0g,  mbF[s]); \
                TMA2D(stg[s] + 32768, mWh, kx, wrow, mbF[s]); \
                TMA2D(stg[s] + 49152, mWl, kx, wrow, mbF[s]); \
            } \
        } while (0)

        int phF0 = 0, phF1 = 0, phD0 = 0, phD1 = 0;
        PTMA(0, 0);
        #pragma unroll 1
        for (int kt = 0; kt < 8; kt++) {
            const int s = kt & 1;
            if (s == 0) { MBARRIER_WAIT_PARITY(mbF[0], phF0 & 1); phF0++; }
            else        { MBARRIER_WAIT_PARITY(mbF[1], phF1 & 1); phF1++; }
            if (el) {
                const uint32_t base = stg[s];
                const uint64_t dAh = MAKE_SMEM_DESC(base);
                const uint64_t dAl = MAKE_SMEM_DESC(base + 16384);
                const uint64_t dBh = MAKE_SMEM_DESC(base + 32768);
                const uint64_t dBl = MAKE_SMEM_DESC(base + 49152);
                #pragma unroll
                for (int n2 = 0; n2 < 2; n2++) {
                    const uint64_t bo_ = (uint64_t)(n2 * 512);
                    const uint32_t dt = tmem + n2 * 64;
                    #pragma unroll
                    for (int sc = 0; sc < 4; sc++) {
                        const bool first = (kt == 0 && sc == 0);
                        tcg_f16_ss(dt, dAh + sc*2, dBh + bo_ + sc*2, IDESC_P, !first);
                        tcg_f16_ss(dt, dAh + sc*2, dBl + bo_ + sc*2, IDESC_P, true);
                        tcg_f16_ss(dt, dAl + sc*2, dBh + bo_ + sc*2, IDESC_P, true);
                    }
                }
                TCGEN05_COMMIT(mbD[s]);
            }
            if (kt < 7) {
                const int s2 = (kt + 1) & 1;
                if (kt >= 1) {
                    // MMA (kt-1) read stage s2; wait its commit before refill
                    if (s2 == 0) { MBARRIER_WAIT_PARITY(mbD[0], phD0 & 1); phD0++; }
                    else         { MBARRIER_WAIT_PARITY(mbD[1], phD1 & 1); phD1++; }
                }
                PTMA(kt + 1, s2);
            }
        }
        #undef PTMA
        // commit(kt=7) on mbD[1] covers ALL prior MMAs by the issuing thread
        MBARRIER_WAIT_PARITY(mbD[1], phD1 & 1);
    }
    __syncthreads();
    TCGEN05_FENCE_AFTER();

    const int mrow = (w & 3)*32 + lane;
    const int cbase = (w >> 2)*64;
    uint32_t dr[64];
    TCGEN05_LD_32X32B_X32(dr, tmem + cbase);
    TCGEN05_LD_32X32B_X32(dr + 32, tmem + cbase + 32);
    TCGEN05_WAIT_LD();
    TCGEN05_FENCE_BEFORE();

    const int t = t0 + mrow;
    if (wsel < 2) {
        __nv_bfloat16* oh = wsel==0 ? g_qhi : g_khi;
        __nv_bfloat16* ol = wsel==0 ? g_qlo : g_klo;
        #pragma unroll
        for (int n = 0; n < 64; n += 2) {
            int o = o0 + cbase + n;
            int hh = o >> 6, d = o & 63;
            float v0 = __uint_as_float(dr[n])   + bias[o];
            float v1 = __uint_as_float(dr[n+1]) + bias[o+1];
            unsigned hi2, lo2;
            cv2(v0, v1, hi2, lo2);
            size_t idx = ((size_t)(b*H_+hh)*T_ + t)*D_ + d;
            *(unsigned*)&oh[idx] = hi2;
            *(unsigned*)&ol[idx] = lo2;
        }
    } else {
        #pragma unroll
        for (int n = 0; n < 64; n++) {
            int o = o0 + cbase + n;
            int hh = o >> 6, d = o & 63;
            float v = __uint_as_float(dr[n]) + bias[o];
            __nv_bfloat16 h0,l0;
            cv(v,h0,l0);
            size_t idx = ((size_t)(b*H_+hh)*D_ + d)*T_ + t;
            g_vhi[idx] = h0;
            g_vlo[idx] = l0;
        }
    }
    __syncthreads();
    if (w == 0) TCGEN05_DEALLOC(tmem, 128);

#else
    // fallback: double-buffered mma.sync (round-9 proven); tensormaps unused
    const __nv_bfloat16* Bh = g_whi + (size_t)wsel*C_*C_;
    const __nv_bfloat16* Bl = g_wlo + (size_t)wsel*C_*C_;
    const int wm = w & 3, wn = w >> 2;
    const int lg = lane >> 2, tg = lane & 3;
    const int l7 = lane & 7, lh = (lane >> 3) & 1, lq = lane >> 4;

    const unsigned SBASE = su32(smem);
    const unsigned STG = 20480;

    float acc[2][8][4] = {};

    const unsigned aHB = SBASE + (wm*32 + lh*8 + l7)*80 + lq*16;
    const unsigned aLB = aHB + 10240;
    const unsigned bHB = SBASE + 40960 + (wn*64 + lq*8 + l7)*80 + lh*16;
    const unsigned bLB = bHB + 10240;

    #define PROJ_PREFETCH(k0, st) do { \
        _Pragma("unroll") \
        for (int r = 0; r < 4; r++) { \
            int s = tid + r*256; \
            int buf = s >> 9, rc = s & 511; \
            int row = rc >> 2, c = rc & 3; \
            unsigned off = (st)*STG + buf*10240 + row*80 + c*16; \
            const __nv_bfloat16* asrc = (buf ? g_xtlo : g_xthi) + (size_t)(m0g+row)*C_ + (k0) + c*8; \
            const __nv_bfloat16* bsrc = (buf ? Bl : Bh) + (size_t)(o0+row)*C_ + (k0) + c*8; \
            cpasync16(SBASE + off, asrc); \
            cpasync16(SBASE + 40960 + off, bsrc); \
        } \
        cp_commit(); \
    } while (0)

    PROJ_PREFETCH(0, 0);

    #pragma unroll 1
    for (int it = 0; it < 16; it++) {
        const int cur = it & 1;
        if (it + 1 < 16) { PROJ_PREFETCH((it+1)*32, cur^1); cp_wait1(); }
        else             { cp_wait0(); }
        __syncthreads();

        const unsigned so = cur * STG;
        #pragma unroll
        for (int ks = 0; ks < 2; ks++) {
            const unsigned ko = ks*32;
            unsigned aH[2][4], aL[2][4];
            #pragma unroll
            for (int mi = 0; mi < 2; mi++) {
                ldsm4(aH[mi][0],aH[mi][1],aH[mi][2],aH[mi][3], aHB + so + mi*16*80 + ko);
                ldsm4(aL[mi][0],aL[mi][1],aL[mi][2],aL[mi][3], aLB + so + mi*16*80 + ko);
            }
            #pragma unroll
            for (int nb = 0; nb < 4; nb++) {
                unsigned bH[4], bL[4];
                ldsm4(bH[0],bH[1],bH[2],bH[3], bHB + so + nb*16*80 + ko);
                ldsm4(bL[0],bL[1],bL[2],bL[3], bLB + so + nb*16*80 + ko);
                #pragma unroll
                for (int mi = 0; mi < 2; mi++) {
                    #pragma unroll
                    for (int t = 0; t < 2; t++) {
                        float* c = acc[mi][nb*2+t];
                        mma16816(c, aH[mi][0],aH[mi][1],aH[mi][2],aH[mi][3], bH[t*2],bH[t*2+1]);
                        mma16816(c, aH[mi][0],aH[mi][1],aH[mi][2],aH[mi][3], bL[t*2],bL[t*2+1]);
                        mma16816(c, aL[mi][0],aL[mi][1],aL[mi][2],aL[mi][3], bH[t*2],bH[t*2+1]);
                    }
                }
            }
        }
        __syncthreads();
    }
    #undef PROJ_PREFETCH

    if (wsel < 2) {
        __nv_bfloat16* oh = wsel==0 ? g_qhi : g_khi;
        __nv_bfloat16* ol = wsel==0 ? g_qlo : g_klo;
        #pragma unroll
        for (int mi = 0; mi < 2; mi++) {
            int tr0 = t0 + wm*32 + mi*16 + lg;
            #pragma unroll
            for (int nj = 0; nj < 8; nj++) {
                int o = o0 + wn*64 + nj*8 + tg*2;
                float bi0 = bias[o], bi1 = bias[o+1];
                int hh = o >> 6, d = o & 63;
                size_t base = ((size_t)(b*H_+hh)*T_ + tr0)*D_ + d;
                __nv_bfloat16 h0,l0,h1,l1;
                cv(acc[mi][nj][0]+bi0, h0,l0); cv(acc[mi][nj][1]+bi1, h1,l1);
                *(unsigned*)&oh[base] = pk2(h0,h1);
                *(unsigned*)&ol[base] = pk2(l0,l1);
                cv(acc[mi][nj][2]+bi0, h0,l0); cv(acc[mi][nj][3]+bi1, h1,l1);
                *(unsigned*)&oh[base + 8*D_] = pk2(h0,h1);
                *(unsigned*)&ol[base + 8*D_] = pk2(l0,l1);
            }
        }
    } else {
        #pragma unroll
        for (int mi = 0; mi < 2; mi++) {
            int tr0 = t0 + wm*32 + mi*16 + lg;
            #pragma unroll
            for (int nj = 0; nj < 8; nj++) {
                int o = o0 + wn*64 + nj*8 + tg*2;
                float bi0 = bias[o], bi1 = bias[o+1];
                int hh = o >> 6, d = o & 63;
                size_t base = ((size_t)(b*H_+hh)*D_ + d)*T_ + tr0;
                __nv_bfloat16 h0,l0;
                cv(acc[mi][nj][0]+bi0, h0,l0); g_vhi[base] = h0;      g_vlo[base] = l0;
                cv(acc[mi][nj][1]+bi1, h0,l0); g_vhi[base+T_] = h0;   g_vlo[base+T_] = l0;
                cv(acc[mi][nj][2]+bi0, h0,l0); g_vhi[base+8] = h0;    g_vlo[base+8] = l0;
                cv(acc[mi][nj][3]+bi1, h0,l0); g_vhi[base+T_+8] = h0; g_vlo[base+T_+8] = l0;
            }
        }
    }
#endif
}

// ---------------------------------------------------------------------
// tc_gemm_256 (round-13, used by outp)
// ---------------------------------------------------------------------
#if HAS_TCGEN05
__device__ __forceinline__ void tc_gemm_256(
    const uint32_t sb, const uint32_t tmem, const int tid, const int w,
    const __nv_bfloat16* Ah, const __nv_bfloat16* Al, const int arow0,
    const __nv_bfloat16* Bh, const __nv_bfloat16* Bl, const int brow0)
{
    for (int kt = 0; kt < 8; kt++) {
        if (kt > 0) MBARRIER_WAIT_PARITY(sb + PT_MB0, (kt-1) & 1);
        __syncthreads();
        const int kc0 = kt * 64;
        #pragma unroll
        for (int r = 0; r < 24; r++) {
            int e = tid + r*256;
            unsigned dst;
            const __nv_bfloat16* src;
            if (e < 2048) {
                int buf = e >> 10;
                int rc = e & 1023;
                int row = rc >> 3, c = rc & 7;
                unsigned doff = (unsigned)((row>>3)*1024 + (row&7)*128 + ((c ^ (row&7))*16));
                dst = sb + (buf ? PT_AL : PT_AH) + doff;
                src = (buf ? Al : Ah) + (size_t)(arow0+row)*C_ + kc0 + c*8;
            } else {
                int e2 = e - 2048;
                int buf = e2 >> 11;
                int rc = e2 & 2047;
                int row = rc >> 3, c = rc & 7;
                unsigned doff = (unsigned)((row>>3)*1024 + (row&7)*128 + ((c ^ (row&7))*16));
                dst = sb + (buf ? PT_BL : PT_BH) + doff;
                src = (buf ? Bl : Bh) + (size_t)(brow0+row)*C_ + kc0 + c*8;
            }
            cpasync16(dst, src);
        }
        cp_commit();
        cp_wait0();
        __syncthreads();
        FENCE_PROXY_ASYNC_SHARED_CTA();

        if (w == 0) {
            if (elect_one_pred()) {
                const uint64_t dAh = MAKE_SMEM_DESC(sb + PT_AH);
                const uint64_t dAl = MAKE_SMEM_DESC(sb + PT_AL);
                const uint64_t dBh = MAKE_SMEM_DESC(sb + PT_BH);
                const uint64_t dBl = MAKE_SMEM_DESC(sb + PT_BL);
                #pragma unroll
                for (int n2 = 0; n2 < 4; n2++) {
                    const uint64_t bo_ = (uint64_t)(n2 * 512);
                    const uint32_t dt = tmem + n2 * 64;
                    #pragma unroll
                    for (int s = 0; s < 4; s++) {
                        const bool first = (kt == 0 && s == 0);
                        tcg_f16_ss(dt, dAh + s*2, dBh + bo_ + s*2, IDESC_P, !first);
                        tcg_f16_ss(dt, dAh + s*2, dBl + bo_ + s*2, IDESC_P, true);
                        tcg_f16_ss(dt, dAl + s*2, dBh + bo_ + s*2, IDESC_P, true);
                    }
                }
                TCGEN05_COMMIT(sb + PT_MB0);
            }
        }
    }
    MBARRIER_WAIT_PARITY(sb + PT_MB0, 1);
    TCGEN05_FENCE_AFTER();
}
#endif

// =====================================================================
// Output projection (round-13): tcgen05 N=256, grid 4 x 32 / fallback
// =====================================================================
__global__ __launch_bounds__(256) void outp_any(
    const float* __restrict__ bo, const float* __restrict__ mask,
    float* __restrict__ out)
{
    extern __shared__ unsigned char smem[];
    const int tid = threadIdx.x, lane = tid & 31, w = tid >> 5;

    const int o0 = blockIdx.x * 128;
    const int n0g = blockIdx.y * 256;
    const int b = n0g >> 10, t0 = n0g & 1023;

    const __nv_bfloat16* Ah = g_whi + (size_t)3*C_*C_;
    const __nv_bfloat16* Al = g_wlo + (size_t)3*C_*C_;

#if HAS_TCGEN05
    const uint32_t sb = su32(smem);
    if (w == 0) TCGEN05_ALLOC(sb + PT_TMEM, 256);
    if (tid == 0) MBARRIER_INIT(sb + PT_MB0, 1);
    __syncthreads();
    uint32_t tmem;
    asm volatile("ld.shared.b32 %0, [%1];" : "=r"(tmem) : "r"(sb + PT_TMEM));

    tc_gemm_256(sb, tmem, tid, w, Ah, Al, o0, g_ythi, g_ytlo, n0g);

    const int o = o0 + (w & 3)*32 + lane;
    const float bov = bo[o];
    uint32_t dr[64];
    #pragma unroll
    for (int pass = 0; pass < 2; pass++) {
        const int cb = (w >> 2)*64 + pass*128;
        TCGEN05_LD_32X32B_X32(dr, tmem + cb);
        TCGEN05_LD_32X32B_X32(dr + 32, tmem + cb + 32);
        TCGEN05_WAIT_LD();
        TCGEN05_FENCE_BEFORE();
        #pragma unroll
        for (int n = 0; n < 64; n += 2) {
            int t = t0 + cb + n;
            float m0v = mask[(size_t)b*T_ + t];
            float m1v = mask[(size_t)b*T_ + t + 1];
            float2 v = make_float2((__uint_as_float(dr[n])   + bov)*m0v,
                                   (__uint_as_float(dr[n+1]) + bov)*m1v);
            *(float2*)&out[((size_t)b*C_ + o)*T_ + t] = v;
        }
    }
    __syncthreads();
    if (w == 0) TCGEN05_DEALLOC(tmem, 256);

#else
    const int wm = w & 3, wn = w >> 2;
    const int lg = lane >> 2, tg = lane & 3;
    const int l7 = lane & 7, lh = (lane >> 3) & 1, lq = lane >> 4;

    const unsigned SBASE = su32(smem);
    const unsigned STG = 20480;

    const unsigned aHB = SBASE + (wm*32 + lh*8 + l7)*80 + lq*16;
    const unsigned aLB = aHB + 10240;
    const unsigned bHB = SBASE + 40960 + (wn*64 + lq*8 + l7)*80 + lh*16;
    const unsigned bLB = bHB + 10240;

    for (int half = 0; half < 2; half++) {
        const int n0gh = n0g + half*128;
        const int t0h = t0 + half*128;
        float acc[2][8][4] = {};

        #define OUTP_PREFETCH(k0, st) do { \
            _Pragma("unroll") \
            for (int r = 0; r < 4; r++) { \
                int s = tid + r*256; \
                int buf = s >> 9, rc = s & 511; \
                int row = rc >> 2, c = rc & 3; \
                unsigned off = (st)*STG + buf*10240 + row*80 + c*16; \
                const __nv_bfloat16* asrc = (buf ? Al : Ah) + (size_t)(o0+row)*C_ + (k0) + c*8; \
                const __nv_bfloat16* bsrc = (buf ? g_ytlo : g_ythi) + (size_t)(n0gh+row)*C_ + (k0) + c*8; \
                cpasync16(SBASE + off, asrc); \
                cpasync16(SBASE + 40960 + off, bsrc); \
            } \
            cp_commit(); \
        } while (0)

        OUTP_PREFETCH(0, 0);

        #pragma unroll 1
        for (int it = 0; it < 16; it++) {
            const int cur = it & 1;
            if (it + 1 < 16) { OUTP_PREFETCH((it+1)*32, cur^1); cp_wait1(); }
            else             { cp_wait0(); }
            __syncthreads();
            const unsigned so = cur * STG;
            #pragma unroll
            for (int ks = 0; ks < 2; ks++) {
                const unsigned ko = ks*32;
                unsigned aH[2][4], aL[2][4];
                #pragma unroll
                for (int mi = 0; mi < 2; mi++) {
                    ldsm4(aH[mi][0],aH[mi][1],aH[mi][2],aH[mi][3], aHB + so + mi*16*80 + ko);
                    ldsm4(aL[mi][0],aL[mi][1],aL[mi][2],aL[mi][3], aLB + so + mi*16*80 + ko);
                }
                #pragma unroll
                for (int nb = 0; nb < 4; nb++) {
                    unsigned bH[4], bL[4];
                    ldsm4(bH[0],bH[1],bH[2],bH[3], bHB + so + nb*16*80 + ko);
                    ldsm4(bL[0],bL[1],bL[2],bL[3], bLB + so + nb*16*80 + ko);
                    #pragma unroll
                    for (int mi = 0; mi < 2; mi++) {
                        #pragma unroll
                        for (int t = 0; t < 2; t++) {
                            float* c = acc[mi][nb*2+t];
                            mma16816(c, aH[mi][0],aH[mi][1],aH[mi][2],aH[mi][3], bH[t*2],bH[t*2+1]);
                            mma16816(c, aH[mi][0],aH[mi][1],aH[mi][2],aH[mi][3], bL[t*2],bL[t*2+1]);
                            mma16816(c, aL[mi][0],aL[mi][1],aL[mi][2],aL[mi][3], bH[t*2],bH[t*2+1]);
                        }
                    }
                }
            }
            __syncthreads();
        }
        #undef OUTP_PREFETCH

        #pragma unroll
        for (int mi = 0; mi < 2; mi++) {
            int o = o0 + wm*32 + mi*16 + lg;
            float bi0 = bo[o], bi1 = bo[o+8];
            #pragma unroll
            for (int nj = 0; nj < 8; nj++) {
                int t = t0h + wn*64 + nj*8 + tg*2;
                float m0v = mask[(size_t)b*T_ + t];
                float m1v = mask[(size_t)b*T_ + t + 1];
                float2 v0 = make_float2((acc[mi][nj][0]+bi0)*m0v, (acc[mi][nj][1]+bi0)*m1v);
                float2 v1 = make_float2((acc[mi][nj][2]+bi1)*m0v, (acc[mi][nj][3]+bi1)*m1v);
                *(float2*)&out[((size_t)b*C_ + o)*T_ + t]     = v0;
                *(float2*)&out[((size_t)b*C_ + o + 8)*T_ + t] = v1;
            }
        }
        __syncthreads();
    }
#endif
}

// =====================================================================
// Fused attention — round-15 version (unchanged, passing at 9.884e-6)
// =====================================================================
__global__ __launch_bounds__(512, 1) void attn_kernel(const float* __restrict__ mask)
{
    extern __shared__ unsigned char smem[];
    __nv_bfloat16* qhi = (__nv_bfloat16*)(smem + OFF_QHI);
    __nv_bfloat16* qlo = (__nv_bfloat16*)(smem + OFF_QLO);
    __nv_bfloat16* khi = (__nv_bfloat16*)(smem + OFF_K);
    __nv_bfloat16* klo = (__nv_bfloat16*)(smem + OFF_K + 18432);
    __nv_bfloat16* vhi = (__nv_bfloat16*)(smem + OFF_V);
    __nv_bfloat16* vlo = (__nv_bfloat16*)(smem + OFF_V + 17408);
    __nv_bfloat16* phi = (__nv_bfloat16*)(smem + OFF_P);
    __nv_bfloat16* plo = (__nv_bfloat16*)(smem + OFF_P + 17408);
    unsigned short* binhi = (unsigned short*)(smem + OFF_SBIN);
    unsigned short* binlo = (unsigned short*)(smem + OFF_BINLO2);
    float* sqr  = (float*)(smem + OFF_SQR);
    float* smk  = (float*)(smem + OFF_SMK);
    float* sstp = (float*)(smem + OFF_SSTP);
    float* sst  = (float*)(smem + OFF_SST);

    const int tid  = threadIdx.x;
    const int lane = tid & 31;
    const int w    = tid >> 5;
    const int wm   = w & 3;
    const int wg   = w >> 2;
    const int lg   = lane >> 2;
    const int tg   = lane & 3;
    const int r0   = wm*16 + lg;
    const int r1   = r0 + 8;
    const int l7   = lane & 7;
    const int lh   = (lane >> 3) & 1;
    const int lq   = lane >> 4;

    const int i0 = blockIdx.x * 64;
    const int h  = blockIdx.y;
    const int b  = blockIdx.z;
    const size_t headbase = (size_t)(b*H_+h)*T_*D_;

    #define STAGE_K(j0k) do { \
        _Pragma("unroll") \
        for (int r = 0; r < 4; r++) { \
            int e = tid + r*512; \
            int bufi = e >> 10; \
            int rc = e & 1023; \
            int j = rc >> 3, c = rc & 7; \
            unsigned dst = su32(bufi ? klo : khi) + j*144 + c*16; \
            const unsigned char* src = \
                (const unsigned char*)(bufi ? g_klo : g_khi) \
                + (headbase + (size_t)((j0k)+j)*D_)*2 + c*16; \
            cpasync16(dst, src); \
        } \
        cp_commit(); \
    } while (0)

    #define STAGE_V(j0v) do { \
        _Pragma("unroll") \
        for (int r = 0; r < 4; r++) { \
            int e = tid + r*512; \
            int bufi = e >> 10; \
            int rc = e & 1023; \
            int d = rc >> 4, c = rc & 15; \
            unsigned dst = su32(bufi ? vlo : vhi) + d*272 + c*16; \
            const unsigned char* src = \
                (const unsigned char*)(bufi ? g_vlo : g_vhi) \
                + (headbase + (size_t)d*T_ + (j0v))*2 + c*16; \
            cpasync16(dst, src); \
        } \
        cp_commit(); \
    } while (0)

    // ---- Phase A: q + erel_k staging; mask; zero bins ----
    #pragma unroll
    for (int r = 0; r < 2; r++) {
        int e = tid + r*512;
        int bufi = e >> 9;
        int rc = e & 511;
        int m = rc >> 3, c = rc & 7;
        unsigned dst = su32(bufi ? qlo : qhi) + m*144 + c*16;
        const unsigned char* src =
            (const unsigned char*)(bufi ? g_qlo : g_qhi)
            + (headbase + (size_t)(i0+m)*D_)*2 + c*16;
        cpasync16(dst, src);
    }
    for (int e = tid; e < REL_*8; e += 512) {
        int r = e >> 3, c = e & 7;
        cpasync16(su32(smem + OFF_EKHI) + r*144 + c*16,
                  (const unsigned char*)g_ekhi + (size_t)(r*64 + c*8)*2);
    }
    for (int e = tid; e < REL_*8; e += 512) {
        int r = e >> 3, c = e & 7;
        cpasync16(su32(smem + OFF_EKLO) + r*144 + c*16,
                  (const unsigned char*)g_eklo + (size_t)(r*64 + c*8)*2);
    }
    cp_commit();
    for (int e = tid; e < T_/4; e += 512)
        ((float4*)smk)[e] = ((const float4*)(mask + (size_t)b*T_))[e];
    for (int e = tid; e < 4608; e += 512) {
        ((unsigned*)binhi)[e] = 0u;
        ((unsigned*)binlo)[e] = 0u;
    }
    cp_wait0();
    __syncthreads();

    const unsigned qhiA = su32(qhi) + (unsigned)((wm*16 + lh*8 + l7)*144 + lq*16);
    const unsigned qloA = su32(qlo) + (unsigned)((wm*16 + lh*8 + l7)*144 + lq*16);

    // ---- Phase B: qrel via MMA ----
    {
        const unsigned ekhiB = su32(smem + OFF_EKHI) + (lq*8 + l7)*144 + lh*16;
        const unsigned ekloB = su32(smem + OFF_EKLO) + (lq*8 + l7)*144 + lh*16;
        float qa[3][2][4] = {};
        const int ng = (wg == 0) ? 3 : 2;
        const int glist[3] = {wg, wg+4, 8};

        #pragma unroll
        for (int ks = 0; ks < 4; ks++) {
            const unsigned ko = ks*32;
            unsigned aH0,aH1,aH2,aH3, aL0,aL1,aL2,aL3;
            ldsm4(aH0,aH1,aH2,aH3, qhiA + ko);
            ldsm4(aL0,aL1,aL2,aL3, qloA + ko);
            for (int gi = 0; gi < ng; gi++) {
                const unsigned ro = glist[gi]*16*144;
                unsigned bH[4], bL[4];
                ldsm4(bH[0],bH[1],bH[2],bH[3], ekhiB + ro + ko);
                ldsm4(bL[0],bL[1],bL[2],bL[3], ekloB + ro + ko);
                #pragma unroll
                for (int t = 0; t < 2; t++) {
                    float* c = qa[gi][t];
                    mma16816(c, aH0,aH1,aH2,aH3, bH[t*2],bH[t*2+1]);
                    mma16816(c, aH0,aH1,aH2,aH3, bL[t*2],bL[t*2+1]);
                    mma16816(c, aL0,aL1,aL2,aL3, bH[t*2],bH[t*2+1]);
                }
            }
        }
        for (int gi = 0; gi < ng; gi++) {
            #pragma unroll
            for (int t = 0; t < 2; t++) {
                int col = glist[gi]*16 + t*8 + tg*2;
                if (col < 136) {
                    *(float2*)&sqr[r0*136 + col] = make_float2(qa[gi][t][0], qa[gi][t][1]);
                    *(float2*)&sqr[r1*136 + col] = make_float2(qa[gi][t][2], qa[gi][t][3]);
                }
            }
        }
    }
    __syncthreads();

    STAGE_K(0);

    const float qrM0 = sqr[r0*136];       const float qrP0 = sqr[r0*136 + 128];
    const float qrM1 = sqr[r1*136];       const float qrP1 = sqr[r1*136 + 128];

    const float scale = 0.125f;
    float yacc[2][4] = {};
    float ls0=0.f, ls1=0.f, ea0=0.f, ea1=0.f, eb0=0.f, eb1=0.f;

    const unsigned khiB0 = su32(khi) + (unsigned)((wg*32 + lq*8 + l7)*144 + lh*16);
    const unsigned kloB0 = su32(klo) + (unsigned)((wg*32 + lq*8 + l7)*144 + lh*16);
    const unsigned phiA = su32(phi) + (unsigned)((wm*16 + lh*8 + l7)*272 + lq*16);
    const unsigned ploA = su32(plo) + (unsigned)((wm*16 + lh*8 + l7)*272 + lq*16);
    const unsigned vhiB = su32(vhi) + (unsigned)((wg*8 + lq*32 + l7)*272 + lh*16);
    const unsigned vloB = su32(vlo) + (unsigned)((wg*8 + lq*32 + l7)*272 + lh*16);

    for (int kt = 0; kt < 8; kt++) {
        const int j0g = kt * 128;
        const int relbase = j0g - i0;
        const bool fastHi = (relbase >= 127);
        const bool fastLo = (relbase <= -191);

        __syncthreads();
        STAGE_V(j0g);
        cp_wait1();
        __syncthreads();

        float sacc[4][4] = {};
        #pragma unroll
        for (int ks = 0; ks < 4; ks++) {
            const unsigned ko = ks*32;
            unsigned aH0,aH1,aH2,aH3, aL0,aL1,aL2,aL3;
            ldsm4(aH0,aH1,aH2,aH3, qhiA + ko);
            ldsm4(aL0,aL1,aL2,aL3, qloA + ko);
            unsigned bH[8], bL[8];
            ldsm4(bH[0],bH[1],bH[2],bH[3], khiB0 + ko);
            ldsm4(bH[4],bH[5],bH[6],bH[7], khiB0 + 16*144 + ko);
            ldsm4(bL[0],bL[1],bL[2],bL[3], kloB0 + ko);
            ldsm4(bL[4],bL[5],bL[6],bL[7], kloB0 + 16*144 + ko);
            #pragma unroll
            for (int t = 0; t < 4; t++) {
                unsigned b0h = bH[t*2], b1h = bH[t*2+1];
                unsigned b0l = bL[t*2], b1l = bL[t*2+1];
                mma16816(sacc[t], aH0,aH1,aH2,aH3, b0h,b1h);
                mma16816(sacc[t], aH0,aH1,aH2,aH3, b0l,b1l);
                mma16816(sacc[t], aL0,aL1,aL2,aL3, b0h,b1h);
            }
        }

        if (fastHi || fastLo) {
            const float c0 = fastHi ? qrP0 : qrM0;
            const float c1 = fastHi ? qrP1 : qrM1;
            float acc0 = 0.f, acc1 = 0.f;
            #pragma unroll
            for (int t = 0; t < 4; t++) {
                const int cb = wg*32 + t*8 + tg*2;
                #pragma unroll
                for (int ii = 0; ii < 2; ii++) {
                    const int rr = ii ? r1 : r0;
                    const float cc = ii ? c1 : c0;
                    float ev[2];
                    #pragma unroll
                    for (int jj = 0; jj < 2; jj++) {
                        int gj = j0g + cb + jj;
                        float s = sacc[t][ii*2+jj]*scale + cc;
                        if (smk[gj] <= 0.f) s = -1e9f;
                        float e = __expf(s);
                        if (ii == 0) acc0 += e; else acc1 += e;
                        ev[jj] = e;
                    }
                    unsigned hi2, lo2;
                    cv2(ev[0], ev[1], hi2, lo2);
                    *(unsigned*)&phi[rr*136 + cb] = hi2;
                    *(unsigned*)&plo[rr*136 + cb] = lo2;
                }
            }
            ls0 += acc0; ls1 += acc1;
            if (fastHi) { eb0 += acc0; eb1 += acc1; }
            else        { ea0 += acc0; ea1 += acc1; }
        } else {
            #pragma unroll
            for (int t = 0; t < 4; t++) {
                const int cb = wg*32 + t*8 + tg*2;
                #pragma unroll
                for (int ii = 0; ii < 2; ii++) {
                    const int rr = ii ? r1 : r0;
                    const int gi = i0 + rr;
                    float ev[2];
                    #pragma unroll
                    for (int jj = 0; jj < 2; jj++) {
                        int gj = j0g + cb + jj;
                        int rel = gj - gi;
                        int relc = rel < -64 ? -64 : (rel > 64 ? 64 : rel);
                        float s = sacc[t][ii*2+jj]*scale + sqr[rr*136 + relc + 64];
                        if (smk[gj] <= 0.f) s = -1e9f;
                        float e = __expf(s);
                        if (ii == 0) ls0 += e; else ls1 += e;
                        if (rel <= -64)      { if (ii == 0) ea0 += e; else ea1 += e; }
                        else if (rel >= 64)  { if (ii == 0) eb0 += e; else eb1 += e; }
                        ev[jj] = e;
                    }
                    unsigned hi2, lo2;
                    cv2(ev[0], ev[1], hi2, lo2);
                    *(unsigned*)&phi[rr*136 + cb] = hi2;
                    *(unsigned*)&plo[rr*136 + cb] = lo2;
                    int relA = j0g + cb - gi;
                    if (relA > -64 && relA < 64) {
                        binhi[rr*144 + relA + 64] = (unsigned short)(hi2 & 0xFFFFu);
                        binlo[rr*144 + relA + 64] = (unsigned short)(lo2 & 0xFFFFu);
                    }
                    int relB = relA + 1;
                    if (relB > -64 && relB < 64) {
                        binhi[rr*144 + relB + 64] = (unsigned short)(hi2 >> 16);
                        binlo[rr*144 + relB + 64] = (unsigned short)(lo2 >> 16);
                    }
                }
            }
        }
        __syncthreads();

        if (kt < 7) {
            STAGE_K(j0g + 128);
            cp_wait1();
        } else {
            cp_wait0();
        }
        __syncthreads();

        #pragma unroll
        for (int ks = 0; ks < 8; ks++) {
            const unsigned ko = ks*32;
            unsigned aH0,aH1,aH2,aH3, aL0,aL1,aL2,aL3;
            ldsm4(aH0,aH1,aH2,aH3, phiA + ko);
            ldsm4(aL0,aL1,aL2,aL3, ploA + ko);
            unsigned bH[4], bL[4];
            ldsm4(bH[0],bH[1],bH[2],bH[3], vhiB + ko);
            ldsm4(bL[0],bL[1],bL[2],bL[3], vloB + ko);
            #pragma unroll
            for (int ti = 0; ti < 2; ti++) {
                unsigned b0h = bH[ti*2], b1h = bH[ti*2+1];
                unsigned b0l = bL[ti*2], b1l = bL[ti*2+1];
                mma16816(yacc[ti], aH0,aH1,aH2,aH3, b0h,b1h);
                mma16816(yacc[ti], aH0,aH1,aH2,aH3, b0l,b1l);
                mma16816(yacc[ti], aL0,aL1,aL2,aL3, b0h,b1h);
            }
        }
    }
    #undef STAGE_K
    #undef STAGE_V
    __syncthreads();

    // ---- stage erel_v^T bf16 (into V/P overlay) ----
    for (int e = tid; e < 64*18; e += 512) {
        int d = e/18, c = e - d*18;
        cpasync16(su32(smem + OFF_EVHI) + d*304 + c*16,
                  (const unsigned char*)g_evhi + (size_t)(d*144 + c*8)*2);
    }
    for (int e = tid; e < 64*18; e += 512) {
        int d = e/18, c = e - d*18;
        cpasync16(su32(smem + OFF_EVLO) + d*304 + c*16,
                  (const unsigned char*)g_evlo + (size_t)(d*144 + c*8)*2);
    }
    cp_commit();

    // ---- stat reduction ----
    {
        float v;
        #define RED_(x) v = x; v += __shfl_xor_sync(~0u, v, 1); v += __shfl_xor_sync(~0u, v, 2); x = v;
        RED_(ls0) RED_(ls1) RED_(ea0) RED_(ea1) RED_(eb0) RED_(eb1)
        #undef RED_
        if (tg == 0) {
            sstp[0*256 + wg*64 + r0] = ls0;  sstp[0*256 + wg*64 + r1] = ls1;
            sstp[1*256 + wg*64 + r0] = ea0;  sstp[1*256 + wg*64 + r1] = ea1;
            sstp[2*256 + wg*64 + r0] = eb0;  sstp[2*256 + wg*64 + r1] = eb1;
        }
    }
    __syncthreads();
    if (tid < 64) {
        float l = 0.f, a = 0.f, c = 0.f;
        #pragma unroll
        for (int g = 0; g < 4; g++) {
            l += sstp[0*256 + g*64 + tid];
            a += sstp[1*256 + g*64 + tid];
            c += sstp[2*256 + g*64 + tid];
        }
        sst[tid] = l;
        __nv_bfloat16 hh, ll;
        cv(a, hh, ll);
        binhi[tid*144]       = *(unsigned short*)&hh;
        binlo[tid*144]       = *(unsigned short*)&ll;
        cv(c, hh, ll);
        binhi[tid*144 + 128] = *(unsigned short*)&hh;
        binlo[tid*144 + 128] = *(unsigned short*)&ll;
    }
    cp_wait0();
    __syncthreads();

    // ---- yacc += bins @ erel_v^T  (M=64, N=64, K=144) ----
    {
        const unsigned binA  = su32(smem + OFF_SBIN)   + (wm*16 + lh*8 + l7)*288 + lq*16;
        const unsigned binAl = su32(smem + OFF_BINLO2) + (wm*16 + lh*8 + l7)*288 + lq*16;
        const unsigned evB   = su32(smem + OFF_EVHI)   + (wg*8 + lq*32 + l7)*304 + lh*16;
        const unsigned evBl  = su32(smem + OFF_EVLO)   + (wg*8 + lq*32 + l7)*304 + lh*16;
        #pragma unroll
        for (int ks = 0; ks < 9; ks++) {
            const unsigned ko = ks*32;
            unsigned aH0,aH1,aH2,aH3, aL0,aL1,aL2,aL3;
            ldsm4(aH0,aH1,aH2,aH3, binA + ko);
            ldsm4(aL0,aL1,aL2,aL3, binAl + ko);
            unsigned bH[4], bL[4];
            ldsm4(bH[0],bH[1],bH[2],bH[3], evB + ko);
            ldsm4(bL[0],bL[1],bL[2],bL[3], evBl + ko);
            #pragma unroll
            for (int ti = 0; ti < 2; ti++) {
                unsigned b0h = bH[ti*2], b1h = bH[ti*2+1];
                unsigned b0l = bL[ti*2], b1l = bL[ti*2+1];
                mma16816(yacc[ti], aH0,aH1,aH2,aH3, b0h,b1h);
                mma16816(yacc[ti], aH0,aH1,aH2,aH3, b0l,b1l);
                mma16816(yacc[ti], aL0,aL1,aL2,aL3, b0h,b1h);
            }
        }
    }

    // ---- final: y = yacc / l ; store yt bf16 hi/lo ----
    {
        const float inv0 = 1.f / sst[r0];
        const float inv1 = 1.f / sst[r1];
        const int dA = wg*8 + tg*2;
        const int dB = dA + 32;
        const int cbase = h*64;
        size_t tb0 = ((size_t)b*T_ + i0 + r0)*C_;
        size_t tb1 = ((size_t)b*T_ + i0 + r1)*C_;
        unsigned hi2, lo2;
        cv2(yacc[0][0]*inv0, yacc[0][1]*inv0, hi2, lo2);
        *(unsigned*)&g_ythi[tb0 + cbase + dA] = hi2;
        *(unsigned*)&g_ytlo[tb0 + cbase + dA] = lo2;
        cv2(yacc[0][2]*inv1, yacc[0][3]*inv1, hi2, lo2);
        *(unsigned*)&g_ythi[tb1 + cbase + dA] = hi2;
        *(unsigned*)&g_ytlo[tb1 + cbase + dA] = lo2;
        cv2(yacc[1][0]*inv0, yacc[1][1]*inv0, hi2, lo2);
        *(unsigned*)&g_ythi[tb0 + cbase + dB] = hi2;
        *(unsigned*)&g_ytlo[tb0 + cbase + dB] = lo2;
        cv2(yacc[1][2]*inv1, yacc[1][3]*inv1, hi2, lo2);
        *(unsigned*)&g_ythi[tb1 + cbase + dB] = hi2;
        *(unsigned*)&g_ytlo[tb1 + cbase + dB] = lo2;
    }
}

// =====================================================================
typedef CUresult (*PFN_encTiled)(
    CUtensorMap*, CUtensorMapDataType, unsigned, void*,
    const unsigned long long*, const unsigned long long*,
    const unsigned*, const unsigned*,
    CUtensorMapInterleave, CUtensorMapSwizzle,
    CUtensorMapL2promotion, CUtensorMapFloatOOBfill);

extern "C" void kernel_launch(void* const* d_in, const int* in_sizes, int n_in,
                              void* d_out, int out_size)
{
    const float* x     = (const float*)d_in[0];
    const float* xmask = (const float*)d_in[1];
    const float* Wq    = (const float*)d_in[2];
    const float* bq    = (const float*)d_in[3];
    const float* Wk    = (const float*)d_in[4];
    const float* bk    = (const float*)d_in[5];
    const float* Wv    = (const float*)d_in[6];
    const float* bv    = (const float*)d_in[7];
    const float* Wo    = (const float*)d_in[8];
    const float* bo    = (const float*)d_in[9];
    const float* erelk = (const float*)d_in[10];
    const float* erelv = (const float*)d_in[11];
    float* out = (float*)d_out;

    cudaFuncSetAttribute(attn_kernel,
                         cudaFuncAttributeMaxDynamicSharedMemorySize, SMEM_BYTES);
    cudaFuncSetAttribute(proj_any,
                         cudaFuncAttributeMaxDynamicSharedMemorySize, PJ2_SMEM);
    cudaFuncSetAttribute(outp_any,
                         cudaFuncAttributeMaxDynamicSharedMemorySize, PO_SMEM);

    // build TMA descriptors (host-side; no -lcuda link dependency)
    CUtensorMap mXh{}, mXl{}, mWh{}, mWl{};
    {
        void* fnp = nullptr;
        cudaDriverEntryPointQueryResult qres;
        cudaGetDriverEntryPoint("cuTensorMapEncodeTiled", &fnp,
                                cudaEnableDefault, &qres);
        PFN_encTiled enc = (PFN_encTiled)fnp;
        void *pxh, *pxl, *pwh, *pwl;
        cudaGetSymbolAddress(&pxh, g_xthi);
        cudaGetSymbolAddress(&pxl, g_xtlo);
        cudaGetSymbolAddress(&pwh, g_whi);
        cudaGetSymbolAddress(&pwl, g_wlo);
        unsigned long long dimsX[2] = { (unsigned long long)C_, (unsigned long long)(B_*T_) };
        unsigned long long strX[1]  = { (unsigned long long)(C_*2) };
        unsigned long long dimsW[2] = { (unsigned long long)C_, (unsigned long long)(4*C_) };
        unsigned long long strW[1]  = { (unsigned long long)(C_*2) };
        unsigned box[2] = { 64u, 128u };
        unsigned es[2]  = { 1u, 1u };
        if (enc) {
            enc(&mXh, CU_TENSOR_MAP_DATA_TYPE_BFLOAT16, 2, pxh, dimsX, strX, box, es,
                CU_TENSOR_MAP_INTERLEAVE_NONE, CU_TENSOR_MAP_SWIZZLE_128B,
                CU_TENSOR_MAP_L2_PROMOTION_L2_128B, CU_TENSOR_MAP_FLOAT_OOB_FILL_NONE);
            enc(&mXl, CU_TENSOR_MAP_DATA_TYPE_BFLOAT16, 2, pxl, dimsX, strX, box, es,
                CU_TENSOR_MAP_INTERLEAVE_NONE, CU_TENSOR_MAP_SWIZZLE_128B,
                CU_TENSOR_MAP_L2_PROMOTION_L2_128B, CU_TENSOR_MAP_FLOAT_OOB_FILL_NONE);
            enc(&mWh, CU_TENSOR_MAP_DATA_TYPE_BFLOAT16, 2, pwh, dimsW, strW, box, es,
                CU_TENSOR_MAP_INTERLEAVE_NONE, CU_TENSOR_MAP_SWIZZLE_128B,
                CU_TENSOR_MAP_L2_PROMOTION_L2_128B, CU_TENSOR_MAP_FLOAT_OOB_FILL_NONE);
            enc(&mWl, CU_TENSOR_MAP_DATA_TYPE_BFLOAT16, 2, pwl, dimsW, strW, box, es,
                CU_TENSOR_MAP_INTERLEAVE_NONE, CU_TENSOR_MAP_SWIZZLE_128B,
                CU_TENSOR_MAP_L2_PROMOTION_L2_128B, CU_TENSOR_MAP_FLOAT_OOB_FILL_NONE);
        }
    }

    conv_x<<<dim3(T_/32, C_/32, B_), 256>>>(x);
    conv_w<<<dim3(C_*C_/256, 4), 256>>>(Wq, Wk, Wv, Wo);
    conv_erel<<<36, 256>>>(erelk, erelv);

    proj_any<<<dim3(64, 12), 256, PJ2_SMEM>>>(mXh, mXl, mWh, mWl, bq, bk, bv);

    attn_kernel<<<dim3(16, H_, B_), 512, SMEM_BYTES>>>(xmask);

    outp_any<<<dim3(4, 32), 256, PO_SMEM>>>(bo, xmask, out);
}

// round 17
// speedup vs baseline: 1.0068x; 1.0068x over previous
#include <cuda_runtime.h>
#include <cuda_bf16.h>
#include <cstdint>

#define B_ 8
#define C_ 512
#define T_ 1024
#define H_ 8
#define D_ 64
#define REL_ 129

#if defined(__CUDA_ARCH_FEAT_SM103_ALL) || defined(__CUDA_ARCH_FEAT_SM100_ALL) || defined(__CUDA_ARCH_FEAT_SM101_ALL)
#define HAS_TCGEN05 1
#else
#define HAS_TCGEN05 0
#endif

// ---------------- scratch (no cudaMalloc allowed) ----------------
__device__ __nv_bfloat16 g_xthi[B_*T_*C_];
__device__ __nv_bfloat16 g_xtlo[B_*T_*C_];
__device__ __nv_bfloat16 g_whi[4*C_*C_];
__device__ __nv_bfloat16 g_wlo[4*C_*C_];
__device__ __nv_bfloat16 g_qhi[B_*H_*T_*D_];
__device__ __nv_bfloat16 g_qlo[B_*H_*T_*D_];
__device__ __nv_bfloat16 g_khi[B_*H_*T_*D_];
__device__ __nv_bfloat16 g_klo[B_*H_*T_*D_];
__device__ __nv_bfloat16 g_vhi[B_*H_*T_*D_];   // (B,H,D,T)
__device__ __nv_bfloat16 g_vlo[B_*H_*T_*D_];
__device__ __nv_bfloat16 g_ythi[B_*T_*C_];
__device__ __nv_bfloat16 g_ytlo[B_*T_*C_];
__device__ __nv_bfloat16 g_ekhi[REL_*D_];
__device__ __nv_bfloat16 g_eklo[REL_*D_];
__device__ __nv_bfloat16 g_evhi[D_*144];
__device__ __nv_bfloat16 g_evlo[D_*144];

// ---------------- attn shared memory ----------------
#define OFF_QHI   0
#define OFF_QLO   9216
#define OFF_K     18432
#define OFF_V     55296
#define OFF_P     90112
#define OFF_SBIN  124928      // binhi bf16 [64][144]; pre-loop: eklo overlay
#define OFF_SQR   158720
#define OFF_SMK   193536
#define OFF_SSTP  197632
#define OFF_SST   200704
#define OFF_BINLO2 201472     // binlo bf16 [64][144]
#define SMEM_BYTES 219904
#define OFF_EVHI  57344
#define OFF_EVLO  76800
// pre-loop erel_k overlays (regions free until main loop)
#define OFF_EKHI2 OFF_P       // ekhi [129][144B] = 18576 <= 34816 (P region)
#define OFF_EKLO2 OFF_SBIN    // eklo [129][144B] = 18576 <= 33792 (SBIN region)

// ---------------- proj (2-stage LDGSTS, N=128) — round-15 proven ----------------
#define PJ2_SMEM 132096
#define PT_TMEM 0
#define PT_MB0  8
#define PT_MB1  16
#define PT_STAGE0 1024
#define PT_STAGE1 (1024+65536)
// ---------------- outp (1-stage, N=256) ----------------
#define PO_SMEM 99840
#define PT_AH   1024
#define PT_AL   17408
#define PT_BH   33792
#define PT_BL   66560
#define IDESC_P 0x8100490u   // kind::f16: F32 acc, BF16xBF16, M=128, N=64

// ---------------- helpers ----------------
__device__ __forceinline__ unsigned pk2(__nv_bfloat16 a, __nv_bfloat16 b) {
    __nv_bfloat162 t = __halves2bfloat162(a, b);
    return *reinterpret_cast<unsigned*>(&t);
}
__device__ __forceinline__ void cv(float x, __nv_bfloat16& h, __nv_bfloat16& l) {
    h = __float2bfloat16(x);
    l = __float2bfloat16(x - __bfloat162float(h));
}
__device__ __forceinline__ void cv2(float v0, float v1, unsigned& hi2, unsigned& lo2) {
    asm("cvt.rn.bf16x2.f32 %0, %1, %2;" : "=r"(hi2) : "f"(v1), "f"(v0));
    float h0 = __uint_as_float(hi2 << 16);
    float h1 = __uint_as_float(hi2 & 0xFFFF0000u);
    float l0 = v0 - h0, l1 = v1 - h1;
    asm("cvt.rn.bf16x2.f32 %0, %1, %2;" : "=r"(lo2) : "f"(l1), "f"(l0));
}
__device__ __forceinline__ unsigned su32(const void* p) {
    return (unsigned)__cvta_generic_to_shared(p);
}
__device__ __forceinline__ void cpasync16(unsigned s, const void* g) {
    asm volatile("cp.async.cg.shared.global [%0], [%1], 16;" :: "r"(s), "l"(g));
}
__device__ __forceinline__ void cp_commit() {
    asm volatile("cp.async.commit_group;" ::: "memory");
}
__device__ __forceinline__ void cp_wait0() {
    asm volatile("cp.async.wait_group 0;" ::: "memory");
}
__device__ __forceinline__ void cp_wait1() {
    asm volatile("cp.async.wait_group 1;" ::: "memory");
}
__device__ __forceinline__ void ldsm4(unsigned& r0, unsigned& r1, unsigned& r2,
                                      unsigned& r3, unsigned addr) {
    asm volatile("ldmatrix.sync.aligned.m8n8.x4.shared.b16 {%0,%1,%2,%3}, [%4];"
                 : "=r"(r0), "=r"(r1), "=r"(r2), "=r"(r3) : "r"(addr));
}
__device__ __forceinline__ void mma16816(float* c, unsigned a0, unsigned a1,
                                         unsigned a2, unsigned a3,
                                         unsigned b0, unsigned b1) {
    asm volatile(
        "mma.sync.aligned.m16n8k16.row.col.f32.bf16.bf16.f32 "
        "{%0,%1,%2,%3}, {%4,%5,%6,%7}, {%8,%9}, {%0,%1,%2,%3};"
        : "+f"(c[0]), "+f"(c[1]), "+f"(c[2]), "+f"(c[3])
        : "r"(a0), "r"(a1), "r"(a2), "r"(a3), "r"(b0), "r"(b1));
}

#if HAS_TCGEN05
__device__ __forceinline__ uint32_t elect_one_pred() {
    uint32_t pred;
    asm volatile(
        "{\n\t.reg .pred p;\n\t"
        "elect.sync _|p, 0xFFFFFFFF;\n\t"
        "selp.b32 %0, 1, 0, p;\n\t}"
        : "=r"(pred));
    return pred;
}
static constexpr uint64_t SMEM_DESC_BASE_SW128 =
    (uint64_t(2)  << 61) | (uint64_t(1) << 46) | (uint64_t(64) << 32) | (uint64_t(1) << 16);
#define MAKE_SMEM_DESC(base_addr) \
    (SMEM_DESC_BASE_SW128 | ((uint64_t)((base_addr) >> 4) & 0x3FFF))
#define TCGEN05_ALLOC(smem_result_addr, nCols) \
    asm volatile("tcgen05.alloc.cta_group::1.sync.aligned.shared::cta.b32 [%0], %1;" \
        :: "r"((uint32_t)(smem_result_addr)), "r"((uint32_t)(nCols)) : "memory")
#define TCGEN05_DEALLOC(tmem_addr, nCols) \
    asm volatile("tcgen05.dealloc.cta_group::1.sync.aligned.b32 %0, %1;" \
        :: "r"(tmem_addr), "r"((uint32_t)(nCols)))
#define TCGEN05_COMMIT(mbar_smem_addr) \
    asm volatile("tcgen05.commit.cta_group::1.mbarrier::arrive::one.shared::cluster.b64 [%0];" \
        :: "r"((uint32_t)(mbar_smem_addr)) : "memory")
#define TCGEN05_FENCE_BEFORE() \
    asm volatile("tcgen05.fence::before_thread_sync;" ::: "memory")
#define TCGEN05_FENCE_AFTER() \
    asm volatile("tcgen05.fence::after_thread_sync;" ::: "memory")
#define TCGEN05_WAIT_LD() \
    asm volatile("tcgen05.wait::ld.sync.aligned;" ::: "memory")
#define FENCE_PROXY_ASYNC_SHARED_CTA() \
    asm volatile("fence.proxy.async.shared::cta;" ::: "memory")
#define TCGEN05_LD_32X32B_X32(r, tmem_addr) \
    asm volatile( \
        "tcgen05.ld.sync.aligned.32x32b.x32.b32 " \
        "{%0, %1, %2, %3, %4, %5, %6, %7, " \
        " %8, %9, %10, %11, %12, %13, %14, %15, " \
        " %16, %17, %18, %19, %20, %21, %22, %23, " \
        " %24, %25, %26, %27, %28, %29, %30, %31}, [%32];" \
        : "=r"((r)[0]),  "=r"((r)[1]),  "=r"((r)[2]),  "=r"((r)[3]), \
          "=r"((r)[4]),  "=r"((r)[5]),  "=r"((r)[6]),  "=r"((r)[7]), \
          "=r"((r)[8]),  "=r"((r)[9]),  "=r"((r)[10]), "=r"((r)[11]), \
          "=r"((r)[12]), "=r"((r)[13]), "=r"((r)[14]), "=r"((r)[15]), \
          "=r"((r)[16]), "=r"((r)[17]), "=r"((r)[18]), "=r"((r)[19]), \
          "=r"((r)[20]), "=r"((r)[21]), "=r"((r)[22]), "=r"((r)[23]), \
          "=r"((r)[24]), "=r"((r)[25]), "=r"((r)[26]), "=r"((r)[27]), \
          "=r"((r)[28]), "=r"((r)[29]), "=r"((r)[30]), "=r"((r)[31]) \
        : "r"(tmem_addr))
__device__ __forceinline__ void tcg_f16_ss(uint32_t d_tmem, uint64_t a_desc,
                                           uint64_t b_desc, uint32_t idesc, bool acc)
{
    uint32_t en = acc ? 1u : 0u;
    asm volatile(
        "{\n\t.reg .pred p;\n\t"
        "setp.ne.u32 p, %5, 0;\n\t"
        "tcgen05.mma.cta_group::1.kind::f16 [%0], %1, %2, %3, {%4,%4,%4,%4}, p;\n\t}"
        :: "r"(d_tmem), "l"(a_desc), "l"(b_desc), "r"(idesc), "r"(0u), "r"(en)
        : "memory");
}
#endif // HAS_TCGEN05

#define MBARRIER_INIT(mbar_smem_addr, count) \
    asm volatile("mbarrier.init.shared.b64 [%0], %1;" \
        :: "r"((uint32_t)(mbar_smem_addr)), "r"((uint32_t)(count)) : "memory")
#define MBARRIER_WAIT_PARITY(mbar_smem_addr, phase_parity) do { \
    uint32_t _mbar = (uint32_t)(mbar_smem_addr); \
    uint32_t _parity = (uint32_t)(phase_parity); \
    uint32_t _done; \
    asm volatile( \
        "{\n\t.reg .pred p;\n\t" \
        "mbarrier.try_wait.parity.acquire.cta.shared::cta.b64 p, [%1], %2;\n\t" \
        "selp.b32 %0, 1, 0, p;\n\t}" \
        : "=r"(_done) : "r"(_mbar), "r"(_parity) : "memory"); \
    if (!_done) { \
        asm volatile( \
            "{\n\t.reg .pred P1;\n\t" \
            "WAIT_LOOP_%=:\n\t" \
            "mbarrier.try_wait.parity.acquire.cta.shared::cta.b64 P1, [%0], %1, 0x989680;\n\t" \
            "@P1 bra.uni WAIT_DONE_%=;\n\t" \
            "bra.uni WAIT_LOOP_%=;\n\t" \
            "WAIT_DONE_%=:\n\t}" \
            :: "r"(_mbar), "r"(_parity) : "memory"); \
    } \
} while(0)

// =====================================================================
// prep kernels (unchanged)
// =====================================================================
__global__ __launch_bounds__(256) void conv_x(const float* __restrict__ x)
{
    __shared__ float s[32][33];
    const int b = blockIdx.z, c0 = blockIdx.y*32, t0 = blockIdx.x*32;
    const int tx = threadIdx.x & 31, ty = threadIdx.x >> 5;
    #pragma unroll
    for (int r = 0; r < 4; r++) {
        int c = ty + r*8;
        s[c][tx] = x[((size_t)b*C_ + c0 + c)*T_ + t0 + tx];
    }
    __syncthreads();
    #pragma unroll
    for (int r = 0; r < 4; r++) {
        int t = ty + r*8;
        float v = s[tx][t];
        __nv_bfloat16 h, l;
        cv(v, h, l);
        size_t idx = ((size_t)b*T_ + t0 + t)*C_ + c0 + tx;
        g_xthi[idx] = h;
        g_xtlo[idx] = l;
    }
}

__global__ __launch_bounds__(256) void conv_w(
    const float* __restrict__ w0, const float* __restrict__ w1,
    const float* __restrict__ w2, const float* __restrict__ w3)
{
    const int g = blockIdx.y;
    const float* W = g==0 ? w0 : g==1 ? w1 : g==2 ? w2 : w3;
    int idx = blockIdx.x*256 + threadIdx.x;
    float v = W[idx];
    __nv_bfloat16 h, l;
    cv(v, h, l);
    g_whi[(size_t)g*C_*C_ + idx] = h;
    g_wlo[(size_t)g*C_*C_ + idx] = l;
}

__global__ __launch_bounds__(256) void conv_erel(
    const float* __restrict__ erelk, const float* __restrict__ erelv)
{
    int idx = blockIdx.x*256 + threadIdx.x;
    if (idx < REL_*D_) {
        __nv_bfloat16 h, l;
        cv(erelk[idx], h, l);
        g_ekhi[idx] = h; g_eklo[idx] = l;
    }
    if (idx < D_*144) {
        int d = idx / 144, r = idx - d*144;
        float v = (r < REL_) ? erelv[r*D_ + d] : 0.f;
        __nv_bfloat16 h, l;
        cv(v, h, l);
        g_evhi[idx] = h; g_evlo[idx] = l;
    }
}

// =====================================================================
// QKV projection — round-15 proven: tcgen05 SS 2-stage LDGSTS (N=128)
// =====================================================================
__global__ __launch_bounds__(256) void proj_any(
    const float* __restrict__ bq, const float* __restrict__ bk,
    const float* __restrict__ bv)
{
    extern __shared__ unsigned char smem[];
    const int tid = threadIdx.x, lane = tid & 31, w = tid >> 5;

    const int ny = blockIdx.y;
    const int wsel = ny >> 2;
    const int o0 = (ny & 3) * 128;
    const int m0g = blockIdx.x * 128;
    const int b = m0g >> 10, t0 = m0g & 1023;

    const __nv_bfloat16* Bh = g_whi + (size_t)wsel*C_*C_;
    const __nv_bfloat16* Bl = g_wlo + (size_t)wsel*C_*C_;
    const float* bias = wsel==0 ? bq : (wsel==1 ? bk : bv);

#if HAS_TCGEN05
    const uint32_t sb = su32(smem);
    if (w == 0) TCGEN05_ALLOC(sb + PT_TMEM, 128);
    if (tid == 0) { MBARRIER_INIT(sb + PT_MB0, 1); MBARRIER_INIT(sb + PT_MB1, 1); }
    __syncthreads();
    uint32_t tmem;
    asm volatile("ld.shared.b32 %0, [%1];" : "=r"(tmem) : "r"(sb + PT_TMEM));

    const uint32_t stg[2] = { sb + PT_STAGE0, sb + PT_STAGE1 };
    const uint32_t mb[2]  = { sb + PT_MB0, sb + PT_MB1 };

    #define PSTAGE(ktv, sbv) do { \
        const int kc0_ = (ktv) * 64; \
        _Pragma("unroll") \
        for (int r = 0; r < 16; r++) { \
            int e = tid + r*256; \
            int tile = e >> 10; \
            int rc = e & 1023; \
            int row = rc >> 3, c = rc & 7; \
            unsigned dstoff = (unsigned)(tile*16384 + (row>>3)*1024 + (row&7)*128 + ((c ^ (row&7))*16)); \
            const __nv_bfloat16* src; \
            if (tile == 0)      src = g_xthi + (size_t)(m0g+row)*C_ + kc0_ + c*8; \
            else if (tile == 1) src = g_xtlo + (size_t)(m0g+row)*C_ + kc0_ + c*8; \
            else if (tile == 2) src = Bh + (size_t)(o0+row)*C_ + kc0_ + c*8; \
            else                src = Bl + (size_t)(o0+row)*C_ + kc0_ + c*8; \
            cpasync16((sbv) + dstoff, src); \
        } \
        cp_commit(); \
    } while (0)

    PSTAGE(0, stg[0]);
    cp_wait0();
    __syncthreads();

    int ph0 = 0, ph1 = 0;
    #pragma unroll 1
    for (int kt = 0; kt < 8; kt++) {
        const int bsel = kt & 1;
        FENCE_PROXY_ASYNC_SHARED_CTA();
        if (w == 0) {
            if (elect_one_pred()) {
                const uint32_t base = stg[bsel];
                const uint64_t dAh = MAKE_SMEM_DESC(base);
                const uint64_t dAl = MAKE_SMEM_DESC(base + 16384);
                const uint64_t dBh = MAKE_SMEM_DESC(base + 32768);
                const uint64_t dBl = MAKE_SMEM_DESC(base + 49152);
                #pragma unroll
                for (int n2 = 0; n2 < 2; n2++) {
                    const uint64_t bo_ = (uint64_t)(n2 * 512);
                    const uint32_t dt = tmem + n2 * 64;
                    #pragma unroll
                    for (int s = 0; s < 4; s++) {
                        const bool first = (kt == 0 && s == 0);
                        tcg_f16_ss(dt, dAh + s*2, dBh + bo_ + s*2, IDESC_P, !first);
                        tcg_f16_ss(dt, dAh + s*2, dBl + bo_ + s*2, IDESC_P, true);
                        tcg_f16_ss(dt, dAl + s*2, dBh + bo_ + s*2, IDESC_P, true);
                    }
                }
                TCGEN05_COMMIT(mb[bsel]);
            }
        }
        if (kt < 7) {
            const int b2 = (kt + 1) & 1;
            if (kt >= 1) {
                if (b2 == 0) { MBARRIER_WAIT_PARITY(mb[0], ph0 & 1); ph0++; }
                else         { MBARRIER_WAIT_PARITY(mb[1], ph1 & 1); ph1++; }
            }
            PSTAGE(kt + 1, stg[b2]);
            cp_wait0();
            __syncthreads();
        }
    }
    #undef PSTAGE
    MBARRIER_WAIT_PARITY(mb[1], ph1 & 1);
    TCGEN05_FENCE_AFTER();

    const int mrow = (w & 3)*32 + lane;
    const int cbase = (w >> 2)*64;
    uint32_t dr[64];
    TCGEN05_LD_32X32B_X32(dr, tmem + cbase);
    TCGEN05_LD_32X32B_X32(dr + 32, tmem + cbase + 32);
    TCGEN05_WAIT_LD();
    TCGEN05_FENCE_BEFORE();

    const int t = t0 + mrow;
    if (wsel < 2) {
        __nv_bfloat16* oh = wsel==0 ? g_qhi : g_khi;
        __nv_bfloat16* ol = wsel==0 ? g_qlo : g_klo;
        #pragma unroll
        for (int n = 0; n < 64; n += 2) {
            int o = o0 + cbase + n;
            int hh = o >> 6, d = o & 63;
            float v0 = __uint_as_float(dr[n])   + bias[o];
            float v1 = __uint_as_float(dr[n+1]) + bias[o+1];
            unsigned hi2, lo2;
            cv2(v0, v1, hi2, lo2);
            size_t idx = ((size_t)(b*H_+hh)*T_ + t)*D_ + d;
            *(unsigned*)&oh[idx] = hi2;
            *(unsigned*)&ol[idx] = lo2;
        }
    } else {
        #pragma unroll
        for (int n = 0; n < 64; n++) {
            int o = o0 + cbase + n;
            int hh = o >> 6, d = o & 63;
            float v = __uint_as_float(dr[n]) + bias[o];
            __nv_bfloat16 h0,l0;
            cv(v,h0,l0);
            size_t idx = ((size_t)(b*H_+hh)*D_ + d)*T_ + t;
            g_vhi[idx] = h0;
            g_vlo[idx] = l0;
        }
    }
    __syncthreads();
    if (w == 0) TCGEN05_DEALLOC(tmem, 128);

#else
    // fallback: double-buffered mma.sync (round-9 proven)
    const int wm = w & 3, wn = w >> 2;
    const int lg = lane >> 2, tg = lane & 3;
    const int l7 = lane & 7, lh = (lane >> 3) & 1, lq = lane >> 4;

    const unsigned SBASE = su32(smem);
    const unsigned STG = 20480;

    float acc[2][8][4] = {};

    const unsigned aHB = SBASE + (wm*32 + lh*8 + l7)*80 + lq*16;
    const unsigned aLB = aHB + 10240;
    const unsigned bHB = SBASE + 40960 + (wn*64 + lq*8 + l7)*80 + lh*16;
    const unsigned bLB = bHB + 10240;

    #define PROJ_PREFETCH(k0, st) do { \
        _Pragma("unroll") \
        for (int r = 0; r < 4; r++) { \
            int s = tid + r*256; \
            int buf = s >> 9, rc = s & 511; \
            int row = rc >> 2, c = rc & 3; \
            unsigned off = (st)*STG + buf*10240 + row*80 + c*16; \
            const __nv_bfloat16* asrc = (buf ? g_xtlo : g_xthi) + (size_t)(m0g+row)*C_ + (k0) + c*8; \
            const __nv_bfloat16* bsrc = (buf ? Bl : Bh) + (size_t)(o0+row)*C_ + (k0) + c*8; \
            cpasync16(SBASE + off, asrc); \
            cpasync16(SBASE + 40960 + off, bsrc); \
        } \
        cp_commit(); \
    } while (0)

    PROJ_PREFETCH(0, 0);

    #pragma unroll 1
    for (int it = 0; it < 16; it++) {
        const int cur = it & 1;
        if (it + 1 < 16) { PROJ_PREFETCH((it+1)*32, cur^1); cp_wait1(); }
        else             { cp_wait0(); }
        __syncthreads();

        const unsigned so = cur * STG;
        #pragma unroll
        for (int ks = 0; ks < 2; ks++) {
            const unsigned ko = ks*32;
            unsigned aH[2][4], aL[2][4];
            #pragma unroll
            for (int mi = 0; mi < 2; mi++) {
                ldsm4(aH[mi][0],aH[mi][1],aH[mi][2],aH[mi][3], aHB + so + mi*16*80 + ko);
                ldsm4(aL[mi][0],aL[mi][1],aL[mi][2],aL[mi][3], aLB + so + mi*16*80 + ko);
            }
            #pragma unroll
            for (int nb = 0; nb < 4; nb++) {
                unsigned bH[4], bL[4];
                ldsm4(bH[0],bH[1],bH[2],bH[3], bHB + so + nb*16*80 + ko);
                ldsm4(bL[0],bL[1],bL[2],bL[3], bLB + so + nb*16*80 + ko);
                #pragma unroll
                for (int mi = 0; mi < 2; mi++) {
                    #pragma unroll
                    for (int t = 0; t < 2; t++) {
                        float* c = acc[mi][nb*2+t];
                        mma16816(c, aH[mi][0],aH[mi][1],aH[mi][2],aH[mi][3], bH[t*2],bH[t*2+1]);
                        mma16816(c, aH[mi][0],aH[mi][1],aH[mi][2],aH[mi][3], bL[t*2],bL[t*2+1]);
                        mma16816(c, aL[mi][0],aL[mi][1],aL[mi][2],aL[mi][3], bH[t*2],bH[t*2+1]);
                    }
                }
            }
        }
        __syncthreads();
    }
    #undef PROJ_PREFETCH

    if (wsel < 2) {
        __nv_bfloat16* oh = wsel==0 ? g_qhi : g_khi;
        __nv_bfloat16* ol = wsel==0 ? g_qlo : g_klo;
        #pragma unroll
        for (int mi = 0; mi < 2; mi++) {
            int tr0 = t0 + wm*32 + mi*16 + lg;
            #pragma unroll
            for (int nj = 0; nj < 8; nj++) {
                int o = o0 + wn*64 + nj*8 + tg*2;
                float bi0 = bias[o], bi1 = bias[o+1];
                int hh = o >> 6, d = o & 63;
                size_t base = ((size_t)(b*H_+hh)*T_ + tr0)*D_ + d;
                __nv_bfloat16 h0,l0,h1,l1;
                cv(acc[mi][nj][0]+bi0, h0,l0); cv(acc[mi][nj][1]+bi1, h1,l1);
                *(unsigned*)&oh[base] = pk2(h0,h1);
                *(unsigned*)&ol[base] = pk2(l0,l1);
                cv(acc[mi][nj][2]+bi0, h0,l0); cv(acc[mi][nj][3]+bi1, h1,l1);
                *(unsigned*)&oh[base + 8*D_] = pk2(h0,h1);
                *(unsigned*)&ol[base + 8*D_] = pk2(l0,l1);
            }
        }
    } else {
        #pragma unroll
        for (int mi = 0; mi < 2; mi++) {
            int tr0 = t0 + wm*32 + mi*16 + lg;
            #pragma unroll
            for (int nj = 0; nj < 8; nj++) {
                int o = o0 + wn*64 + nj*8 + tg*2;
                float bi0 = bias[o], bi1 = bias[o+1];
                int hh = o >> 6, d = o & 63;
                size_t base = ((size_t)(b*H_+hh)*D_ + d)*T_ + tr0;
                __nv_bfloat16 h0,l0;
                cv(acc[mi][nj][0]+bi0, h0,l0); g_vhi[base] = h0;      g_vlo[base] = l0;
                cv(acc[mi][nj][1]+bi1, h0,l0); g_vhi[base+T_] = h0;   g_vlo[base+T_] = l0;
                cv(acc[mi][nj][2]+bi0, h0,l0); g_vhi[base+8] = h0;    g_vlo[base+8] = l0;
                cv(acc[mi][nj][3]+bi1, h0,l0); g_vhi[base+T_+8] = h0; g_vlo[base+T_+8] = l0;
            }
        }
    }
#endif
}

// ---------------------------------------------------------------------
// tc_gemm_256 (round-13, used by outp)
// ---------------------------------------------------------------------
#if HAS_TCGEN05
__device__ __forceinline__ void tc_gemm_256(
    const uint32_t sb, const uint32_t tmem, const int tid, const int w,
    const __nv_bfloat16* Ah, const __nv_bfloat16* Al, const int arow0,
    const __nv_bfloat16* Bh, const __nv_bfloat16* Bl, const int brow0)
{
    for (int kt = 0; kt < 8; kt++) {
        if (kt > 0) MBARRIER_WAIT_PARITY(sb + PT_MB0, (kt-1) & 1);
        __syncthreads();
        const int kc0 = kt * 64;
        #pragma unroll
        for (int r = 0; r < 24; r++) {
            int e = tid + r*256;
            unsigned dst;
            const __nv_bfloat16* src;
            if (e < 2048) {
                int buf = e >> 10;
                int rc = e & 1023;
                int row = rc >> 3, c = rc & 7;
                unsigned doff = (unsigned)((row>>3)*1024 + (row&7)*128 + ((c ^ (row&7))*16));
                dst = sb + (buf ? PT_AL : PT_AH) + doff;
                src = (buf ? Al : Ah) + (size_t)(arow0+row)*C_ + kc0 + c*8;
            } else {
                int e2 = e - 2048;
                int buf = e2 >> 11;
                int rc = e2 & 2047;
                int row = rc >> 3, c = rc & 7;
                unsigned doff = (unsigned)((row>>3)*1024 + (row&7)*128 + ((c ^ (row&7))*16));
                dst = sb + (buf ? PT_BL : PT_BH) + doff;
                src = (buf ? Bl : Bh) + (size_t)(brow0+row)*C_ + kc0 + c*8;
            }
            cpasync16(dst, src);
        }
        cp_commit();
        cp_wait0();
        __syncthreads();
        FENCE_PROXY_ASYNC_SHARED_CTA();

        if (w == 0) {
            if (elect_one_pred()) {
                const uint64_t dAh = MAKE_SMEM_DESC(sb + PT_AH);
                const uint64_t dAl = MAKE_SMEM_DESC(sb + PT_AL);
                const uint64_t dBh = MAKE_SMEM_DESC(sb + PT_BH);
                const uint64_t dBl = MAKE_SMEM_DESC(sb + PT_BL);
                #pragma unroll
                for (int n2 = 0; n2 < 4; n2++) {
                    const uint64_t bo_ = (uint64_t)(n2 * 512);
                    const uint32_t dt = tmem + n2 * 64;
                    #pragma unroll
                    for (int s = 0; s < 4; s++) {
                        const bool first = (kt == 0 && s == 0);
                        tcg_f16_ss(dt, dAh + s*2, dBh + bo_ + s*2, IDESC_P, !first);
                        tcg_f16_ss(dt, dAh + s*2, dBl + bo_ + s*2, IDESC_P, true);
                        tcg_f16_ss(dt, dAl + s*2, dBh + bo_ + s*2, IDESC_P, true);
                    }
                }
                TCGEN05_COMMIT(sb + PT_MB0);
            }
        }
    }
    MBARRIER_WAIT_PARITY(sb + PT_MB0, 1);
    TCGEN05_FENCE_AFTER();
}
#endif

// =====================================================================
// Output projection (round-13): tcgen05 N=256, grid 4 x 32 / fallback
// =====================================================================
__global__ __launch_bounds__(256) void outp_any(
    const float* __restrict__ bo, const float* __restrict__ mask,
    float* __restrict__ out)
{
    extern __shared__ unsigned char smem[];
    const int tid = threadIdx.x, lane = tid & 31, w = tid >> 5;

    const int o0 = blockIdx.x * 128;
    const int n0g = blockIdx.y * 256;
    const int b = n0g >> 10, t0 = n0g & 1023;

    const __nv_bfloat16* Ah = g_whi + (size_t)3*C_*C_;
    const __nv_bfloat16* Al = g_wlo + (size_t)3*C_*C_;

#if HAS_TCGEN05
    const uint32_t sb = su32(smem);
    if (w == 0) TCGEN05_ALLOC(sb + PT_TMEM, 256);
    if (tid == 0) MBARRIER_INIT(sb + PT_MB0, 1);
    __syncthreads();
    uint32_t tmem;
    asm volatile("ld.shared.b32 %0, [%1];" : "=r"(tmem) : "r"(sb + PT_TMEM));

    tc_gemm_256(sb, tmem, tid, w, Ah, Al, o0, g_ythi, g_ytlo, n0g);

    const int o = o0 + (w & 3)*32 + lane;
    const float bov = bo[o];
    uint32_t dr[64];
    #pragma unroll
    for (int pass = 0; pass < 2; pass++) {
        const int cb = (w >> 2)*64 + pass*128;
        TCGEN05_LD_32X32B_X32(dr, tmem + cb);
        TCGEN05_LD_32X32B_X32(dr + 32, tmem + cb + 32);
        TCGEN05_WAIT_LD();
        TCGEN05_FENCE_BEFORE();
        #pragma unroll
        for (int n = 0; n < 64; n += 2) {
            int t = t0 + cb + n;
            float m0v = mask[(size_t)b*T_ + t];
            float m1v = mask[(size_t)b*T_ + t + 1];
            float2 v = make_float2((__uint_as_float(dr[n])   + bov)*m0v,
                                   (__uint_as_float(dr[n+1]) + bov)*m1v);
            *(float2*)&out[((size_t)b*C_ + o)*T_ + t] = v;
        }
    }
    __syncthreads();
    if (w == 0) TCGEN05_DEALLOC(tmem, 256);

#else
    const int wm = w & 3, wn = w >> 2;
    const int lg = lane >> 2, tg = lane & 3;
    const int l7 = lane & 7, lh = (lane >> 3) & 1, lq = lane >> 4;

    const unsigned SBASE = su32(smem);
    const unsigned STG = 20480;

    const unsigned aHB = SBASE + (wm*32 + lh*8 + l7)*80 + lq*16;
    const unsigned aLB = aHB + 10240;
    const unsigned bHB = SBASE + 40960 + (wn*64 + lq*8 + l7)*80 + lh*16;
    const unsigned bLB = bHB + 10240;

    for (int half = 0; half < 2; half++) {
        const int n0gh = n0g + half*128;
        const int t0h = t0 + half*128;
        float acc[2][8][4] = {};

        #define OUTP_PREFETCH(k0, st) do { \
            _Pragma("unroll") \
            for (int r = 0; r < 4; r++) { \
                int s = tid + r*256; \
                int buf = s >> 9, rc = s & 511; \
                int row = rc >> 2, c = rc & 3; \
                unsigned off = (st)*STG + buf*10240 + row*80 + c*16; \
                const __nv_bfloat16* asrc = (buf ? Al : Ah) + (size_t)(o0+row)*C_ + (k0) + c*8; \
                const __nv_bfloat16* bsrc = (buf ? g_ytlo : g_ythi) + (size_t)(n0gh+row)*C_ + (k0) + c*8; \
                cpasync16(SBASE + off, asrc); \
                cpasync16(SBASE + 40960 + off, bsrc); \
            } \
            cp_commit(); \
        } while (0)

        OUTP_PREFETCH(0, 0);

        #pragma unroll 1
        for (int it = 0; it < 16; it++) {
            const int cur = it & 1;
            if (it + 1 < 16) { OUTP_PREFETCH((it+1)*32, cur^1); cp_wait1(); }
            else             { cp_wait0(); }
            __syncthreads();
            const unsigned so = cur * STG;
            #pragma unroll
            for (int ks = 0; ks < 2; ks++) {
                const unsigned ko = ks*32;
                unsigned aH[2][4], aL[2][4];
                #pragma unroll
                for (int mi = 0; mi < 2; mi++) {
                    ldsm4(aH[mi][0],aH[mi][1],aH[mi][2],aH[mi][3], aHB + so + mi*16*80 + ko);
                    ldsm4(aL[mi][0],aL[mi][1],aL[mi][2],aL[mi][3], aLB + so + mi*16*80 + ko);
                }
                #pragma unroll
                for (int nb = 0; nb < 4; nb++) {
                    unsigned bH[4], bL[4];
                    ldsm4(bH[0],bH[1],bH[2],bH[3], bHB + so + nb*16*80 + ko);
                    ldsm4(bL[0],bL[1],bL[2],bL[3], bLB + so + nb*16*80 + ko);
                    #pragma unroll
                    for (int mi = 0; mi < 2; mi++) {
                        #pragma unroll
                        for (int t = 0; t < 2; t++) {
                            float* c = acc[mi][nb*2+t];
                            mma16816(c, aH[mi][0],aH[mi][1],aH[mi][2],aH[mi][3], bH[t*2],bH[t*2+1]);
                            mma16816(c, aH[mi][0],aH[mi][1],aH[mi][2],aH[mi][3], bL[t*2],bL[t*2+1]);
                            mma16816(c, aL[mi][0],aL[mi][1],aL[mi][2],aL[mi][3], bH[t*2],bH[t*2+1]);
                        }
                    }
                }
            }
            __syncthreads();
        }
        #undef OUTP_PREFETCH

        #pragma unroll
        for (int mi = 0; mi < 2; mi++) {
            int o = o0 + wm*32 + mi*16 + lg;
            float bi0 = bo[o], bi1 = bo[o+8];
            #pragma unroll
            for (int nj = 0; nj < 8; nj++) {
                int t = t0h + wn*64 + nj*8 + tg*2;
                float m0v = mask[(size_t)b*T_ + t];
                float m1v = mask[(size_t)b*T_ + t + 1];
                float2 v0 = make_float2((acc[mi][nj][0]+bi0)*m0v, (acc[mi][nj][1]+bi0)*m1v);
                float2 v1 = make_float2((acc[mi][nj][2]+bi1)*m0v, (acc[mi][nj][3]+bi1)*m1v);
                *(float2*)&out[((size_t)b*C_ + o)*T_ + t]     = v0;
                *(float2*)&out[((size_t)b*C_ + o + 8)*T_ + t] = v1;
            }
        }
        __syncthreads();
    }
#endif
}

// =====================================================================
// Fused attention — round-15 + early K(0) staging + additive mask.
// =====================================================================
__global__ __launch_bounds__(512, 1) void attn_kernel(const float* __restrict__ mask)
{
    extern __shared__ unsigned char smem[];
    __nv_bfloat16* qhi = (__nv_bfloat16*)(smem + OFF_QHI);
    __nv_bfloat16* qlo = (__nv_bfloat16*)(smem + OFF_QLO);
    __nv_bfloat16* khi = (__nv_bfloat16*)(smem + OFF_K);
    __nv_bfloat16* klo = (__nv_bfloat16*)(smem + OFF_K + 18432);
    __nv_bfloat16* vhi = (__nv_bfloat16*)(smem + OFF_V);
    __nv_bfloat16* vlo = (__nv_bfloat16*)(smem + OFF_V + 17408);
    __nv_bfloat16* phi = (__nv_bfloat16*)(smem + OFF_P);
    __nv_bfloat16* plo = (__nv_bfloat16*)(smem + OFF_P + 17408);
    unsigned short* binhi = (unsigned short*)(smem + OFF_SBIN);
    unsigned short* binlo = (unsigned short*)(smem + OFF_BINLO2);
    float* sqr  = (float*)(smem + OFF_SQR);
    float* smk  = (float*)(smem + OFF_SMK);     // additive mask: 0 or -1e9
    float* sstp = (float*)(smem + OFF_SSTP);
    float* sst  = (float*)(smem + OFF_SST);

    const int tid  = threadIdx.x;
    const int lane = tid & 31;
    const int w    = tid >> 5;
    const int wm   = w & 3;
    const int wg   = w >> 2;
    const int lg   = lane >> 2;
    const int tg   = lane & 3;
    const int r0   = wm*16 + lg;
    const int r1   = r0 + 8;
    const int l7   = lane & 7;
    const int lh   = (lane >> 3) & 1;
    const int lq   = lane >> 4;

    const int i0 = blockIdx.x * 64;
    const int h  = blockIdx.y;
    const int b  = blockIdx.z;
    const size_t headbase = (size_t)(b*H_+h)*T_*D_;

    #define STAGE_K(j0k) do { \
        _Pragma("unroll") \
        for (int r = 0; r < 4; r++) { \
            int e = tid + r*512; \
            int bufi = e >> 10; \
            int rc = e & 1023; \
            int j = rc >> 3, c = rc & 7; \
            unsigned dst = su32(bufi ? klo : khi) + j*144 + c*16; \
            const unsigned char* src = \
                (const unsigned char*)(bufi ? g_klo : g_khi) \
                + (headbase + (size_t)((j0k)+j)*D_)*2 + c*16; \
            cpasync16(dst, src); \
        } \
        cp_commit(); \
    } while (0)

    #define STAGE_V(j0v) do { \
        _Pragma("unroll") \
        for (int r = 0; r < 4; r++) { \
            int e = tid + r*512; \
            int bufi = e >> 10; \
            int rc = e & 1023; \
            int d = rc >> 4, c = rc & 15; \
            unsigned dst = su32(bufi ? vlo : vhi) + d*272 + c*16; \
            const unsigned char* src = \
                (const unsigned char*)(bufi ? g_vlo : g_vhi) \
                + (headbase + (size_t)d*T_ + (j0v))*2 + c*16; \
            cpasync16(dst, src); \
        } \
        cp_commit(); \
    } while (0)

    // ---- Phase A: q + erel_k (P/SBIN overlays) staging [group1];
    //      K(0) staging [group2]; additive mask; zero binlo ----
    #pragma unroll
    for (int r = 0; r < 2; r++) {
        int e = tid + r*512;
        int bufi = e >> 9;
        int rc = e & 511;
        int m = rc >> 3, c = rc & 7;
        unsigned dst = su32(bufi ? qlo : qhi) + m*144 + c*16;
        const unsigned char* src =
            (const unsigned char*)(bufi ? g_qlo : g_qhi)
            + (headbase + (size_t)(i0+m)*D_)*2 + c*16;
        cpasync16(dst, src);
    }
    for (int e = tid; e < REL_*8; e += 512) {
        int r = e >> 3, c = e & 7;
        cpasync16(su32(smem + OFF_EKHI2) + r*144 + c*16,
                  (const unsigned char*)g_ekhi + (size_t)(r*64 + c*8)*2);
    }
    for (int e = tid; e < REL_*8; e += 512) {
        int r = e >> 3, c = e & 7;
        cpasync16(su32(smem + OFF_EKLO2) + r*144 + c*16,
                  (const unsigned char*)g_eklo + (size_t)(r*64 + c*8)*2);
    }
    cp_commit();          // group 1: q + erel_k
    STAGE_K(0);           // group 2: K chunk 0 (in flight through qrel)
    for (int e = tid; e < T_/4; e += 512) {
        float4 m4 = ((const float4*)(mask + (size_t)b*T_))[e];
        m4.x = (m4.x > 0.f) ? 0.f : -1e9f;
        m4.y = (m4.y > 0.f) ? 0.f : -1e9f;
        m4.z = (m4.z > 0.f) ? 0.f : -1e9f;
        m4.w = (m4.w > 0.f) ? 0.f : -1e9f;
        ((float4*)smk)[e] = m4;
    }
    for (int e = tid; e < 4608; e += 512)
        ((unsigned*)binlo)[e] = 0u;
    cp_wait1();           // group 1 arrived; K(0) still in flight
    __syncthreads();

    const unsigned qhiA = su32(qhi) + (unsigned)((wm*16 + lh*8 + l7)*144 + lq*16);
    const unsigned qloA = su32(qlo) + (unsigned)((wm*16 + lh*8 + l7)*144 + lq*16);

    // ---- Phase B: qrel via MMA (erel_k read from P/SBIN overlays) ----
    {
        const unsigned ekhiB = su32(smem + OFF_EKHI2) + (lq*8 + l7)*144 + lh*16;
        const unsigned ekloB = su32(smem + OFF_EKLO2) + (lq*8 + l7)*144 + lh*16;
        float qa[3][2][4] = {};
        const int ng = (wg == 0) ? 3 : 2;
        const int glist[3] = {wg, wg+4, 8};

        #pragma unroll
        for (int ks = 0; ks < 4; ks++) {
            const unsigned ko = ks*32;
            unsigned aH0,aH1,aH2,aH3, aL0,aL1,aL2,aL3;
            ldsm4(aH0,aH1,aH2,aH3, qhiA + ko);
            ldsm4(aL0,aL1,aL2,aL3, qloA + ko);
            for (int gi = 0; gi < ng; gi++) {
                const unsigned ro = glist[gi]*16*144;
                unsigned bH[4], bL[4];
                ldsm4(bH[0],bH[1],bH[2],bH[3], ekhiB + ro + ko);
                ldsm4(bL[0],bL[1],bL[2],bL[3], ekloB + ro + ko);
                #pragma unroll
                for (int t = 0; t < 2; t++) {
                    float* c = qa[gi][t];
                    mma16816(c, aH0,aH1,aH2,aH3, bH[t*2],bH[t*2+1]);
                    mma16816(c, aH0,aH1,aH2,aH3, bL[t*2],bL[t*2+1]);
                    mma16816(c, aL0,aL1,aL2,aL3, bH[t*2],bH[t*2+1]);
                }
            }
        }
        for (int gi = 0; gi < ng; gi++) {
            #pragma unroll
            for (int t = 0; t < 2; t++) {
                int col = glist[gi]*16 + t*8 + tg*2;
                if (col < 136) {
                    *(float2*)&sqr[r0*136 + col] = make_float2(qa[gi][t][0], qa[gi][t][1]);
                    *(float2*)&sqr[r1*136 + col] = make_float2(qa[gi][t][2], qa[gi][t][3]);
                }
            }
        }
    }
    __syncthreads();   // qrel done reading overlays (P/SBIN now free)

    // zero binhi (overlay released); visible after first loop barrier
    for (int e = tid; e < 4608; e += 512)
        ((unsigned*)binhi)[e] = 0u;

    const float qrM0 = sqr[r0*136];       const float qrP0 = sqr[r0*136 + 128];
    const float qrM1 = sqr[r1*136];       const float qrP1 = sqr[r1*136 + 128];

    const float scale = 0.125f;
    float yacc[2][4] = {};
    float ls0=0.f, ls1=0.f, ea0=0.f, ea1=0.f, eb0=0.f, eb1=0.f;

    const unsigned khiB0 = su32(khi) + (unsigned)((wg*32 + lq*8 + l7)*144 + lh*16);
    const unsigned kloB0 = su32(klo) + (unsigned)((wg*32 + lq*8 + l7)*144 + lh*16);
    const unsigned phiA = su32(phi) + (unsigned)((wm*16 + lh*8 + l7)*272 + lq*16);
    const unsigned ploA = su32(plo) + (unsigned)((wm*16 + lh*8 + l7)*272 + lq*16);
    const unsigned vhiB = su32(vhi) + (unsigned)((wg*8 + lq*32 + l7)*272 + lh*16);
    const unsigned vloB = su32(vlo) + (unsigned)((wg*8 + lq*32 + l7)*272 + lh*16);

    for (int kt = 0; kt < 8; kt++) {
        const int j0g = kt * 128;
        const int relbase = j0g - i0;
        const bool fastHi = (relbase >= 127);
        const bool fastLo = (relbase <= -191);

        __syncthreads();
        STAGE_V(j0g);
        cp_wait1();        // K(kt) arrived; V(kt) in flight
        __syncthreads();

        float sacc[4][4] = {};
        #pragma unroll
        for (int ks = 0; ks < 4; ks++) {
            const unsigned ko = ks*32;
            unsigned aH0,aH1,aH2,aH3, aL0,aL1,aL2,aL3;
            ldsm4(aH0,aH1,aH2,aH3, qhiA + ko);
            ldsm4(aL0,aL1,aL2,aL3, qloA + ko);
            unsigned bH[8], bL[8];
            ldsm4(bH[0],bH[1],bH[2],bH[3], khiB0 + ko);
            ldsm4(bH[4],bH[5],bH[6],bH[7], khiB0 + 16*144 + ko);
            ldsm4(bL[0],bL[1],bL[2],bL[3], kloB0 + ko);
            ldsm4(bL[4],bL[5],bL[6],bL[7], kloB0 + 16*144 + ko);
            #pragma unroll
            for (int t = 0; t < 4; t++) {
                unsigned b0h = bH[t*2], b1h = bH[t*2+1];
                unsigned b0l = bL[t*2], b1l = bL[t*2+1];
                mma16816(sacc[t], aH0,aH1,aH2,aH3, b0h,b1h);
                mma16816(sacc[t], aH0,aH1,aH2,aH3, b0l,b1l);
                mma16816(sacc[t], aL0,aL1,aL2,aL3, b0h,b1h);
            }
        }

        if (fastHi || fastLo) {
            const float c0 = fastHi ? qrP0 : qrM0;
            const float c1 = fastHi ? qrP1 : qrM1;
            float acc0 = 0.f, acc1 = 0.f;
            #pragma unroll
            for (int t = 0; t < 4; t++) {
                const int cb = wg*32 + t*8 + tg*2;
                #pragma unroll
                for (int ii = 0; ii < 2; ii++) {
                    const int rr = ii ? r1 : r0;
                    const float cc = ii ? c1 : c0;
                    float ev[2];
                    #pragma unroll
                    for (int jj = 0; jj < 2; jj++) {
                        int gj = j0g + cb + jj;
                        float s = sacc[t][ii*2+jj]*scale + cc + smk[gj];
                        float e = __expf(s);
                        if (ii == 0) acc0 += e; else acc1 += e;
                        ev[jj] = e;
                    }
                    unsigned hi2, lo2;
                    cv2(ev[0], ev[1], hi2, lo2);
                    *(unsigned*)&phi[rr*136 + cb] = hi2;
                    *(unsigned*)&plo[rr*136 + cb] = lo2;
                }
            }
            ls0 += acc0; ls1 += acc1;
            if (fastHi) { eb0 += acc0; eb1 += acc1; }
            else        { ea0 += acc0; ea1 += acc1; }
        } else {
            #pragma unroll
            for (int t = 0; t < 4; t++) {
                const int cb = wg*32 + t*8 + tg*2;
                #pragma unroll
                for (int ii = 0; ii < 2; ii++) {
                    const int rr = ii ? r1 : r0;
                    const int gi = i0 + rr;
                    float ev[2];
                    #pragma unroll
                    for (int jj = 0; jj < 2; jj++) {
                        int gj = j0g + cb + jj;
                        int rel = gj - gi;
                        int relc = rel < -64 ? -64 : (rel > 64 ? 64 : rel);
                        float s = sacc[t][ii*2+jj]*scale + sqr[rr*136 + relc + 64] + smk[gj];
                        float e = __expf(s);
                        if (ii == 0) ls0 += e; else ls1 += e;
                        if (rel <= -64)      { if (ii == 0) ea0 += e; else ea1 += e; }
                        else if (rel >= 64)  { if (ii == 0) eb0 += e; else eb1 += e; }
                        ev[jj] = e;
                    }
                    unsigned hi2, lo2;
                    cv2(ev[0], ev[1], hi2, lo2);
                    *(unsigned*)&phi[rr*136 + cb] = hi2;
                    *(unsigned*)&plo[rr*136 + cb] = lo2;
                    int relA = j0g + cb - gi;
                    if (relA > -64 && relA < 64) {
                        binhi[rr*144 + relA + 64] = (unsigned short)(hi2 & 0xFFFFu);
                        binlo[rr*144 + relA + 64] = (unsigned short)(lo2 & 0xFFFFu);
                    }
                    int relB = relA + 1;
                    if (relB > -64 && relB < 64) {
                        binhi[rr*144 + relB + 64] = (unsigned short)(hi2 >> 16);
                        binlo[rr*144 + relB + 64] = (unsigned short)(lo2 >> 16);
                    }
                }
            }
        }
        __syncthreads();

        if (kt < 7) {
            STAGE_K(j0g + 128);
            cp_wait1();
        } else {
            cp_wait0();
        }
        __syncthreads();

        #pragma unroll
        for (int ks = 0; ks < 8; ks++) {
            const unsigned ko = ks*32;
            unsigned aH0,aH1,aH2,aH3, aL0,aL1,aL2,aL3;
            ldsm4(aH0,aH1,aH2,aH3, phiA + ko);
            ldsm4(aL0,aL1,aL2,aL3, ploA + ko);
            unsigned bH[4], bL[4];
            ldsm4(bH[0],bH[1],bH[2],bH[3], vhiB + ko);
            ldsm4(bL[0],bL[1],bL[2],bL[3], vloB + ko);
            #pragma unroll
            for (int ti = 0; ti < 2; ti++) {
                unsigned b0h = bH[ti*2], b1h = bH[ti*2+1];
                unsigned b0l = bL[ti*2], b1l = bL[ti*2+1];
                mma16816(yacc[ti], aH0,aH1,aH2,aH3, b0h,b1h);
                mma16816(yacc[ti], aH0,aH1,aH2,aH3, b0l,b1l);
                mma16816(yacc[ti], aL0,aL1,aL2,aL3, b0h,b1h);
            }
        }
    }
    #undef STAGE_K
    #undef STAGE_V
    __syncthreads();

    // ---- stage erel_v^T bf16 (into V/P overlay) ----
    for (int e = tid; e < 64*18; e += 512) {
        int d = e/18, c = e - d*18;
        cpasync16(su32(smem + OFF_EVHI) + d*304 + c*16,
                  (const unsigned char*)g_evhi + (size_t)(d*144 + c*8)*2);
    }
    for (int e = tid; e < 64*18; e += 512) {
        int d = e/18, c = e - d*18;
        cpasync16(su32(smem + OFF_EVLO) + d*304 + c*16,
                  (const unsigned char*)g_evlo + (size_t)(d*144 + c*8)*2);
    }
    cp_commit();

    // ---- stat reduction ----
    {
        float v;
        #define RED_(x) v = x; v += __shfl_xor_sync(~0u, v, 1); v += __shfl_xor_sync(~0u, v, 2); x = v;
        RED_(ls0) RED_(ls1) RED_(ea0) RED_(ea1) RED_(eb0) RED_(eb1)
        #undef RED_
        if (tg == 0) {
            sstp[0*256 + wg*64 + r0] = ls0;  sstp[0*256 + wg*64 + r1] = ls1;
            sstp[1*256 + wg*64 + r0] = ea0;  sstp[1*256 + wg*64 + r1] = ea1;
            sstp[2*256 + wg*64 + r0] = eb0;  sstp[2*256 + wg*64 + r1] = eb1;
        }
    }
    __syncthreads();
    if (tid < 64) {
        float l = 0.f, a = 0.f, c = 0.f;
        #pragma unroll
        for (int g = 0; g < 4; g++) {
            l += sstp[0*256 + g*64 + tid];
            a += sstp[1*256 + g*64 + tid];
            c += sstp[2*256 + g*64 + tid];
        }
        sst[tid] = l;
        __nv_bfloat16 hh, ll;
        cv(a, hh, ll);
        binhi[tid*144]       = *(unsigned short*)&hh;
        binlo[tid*144]       = *(unsigned short*)&ll;
        cv(c, hh, ll);
        binhi[tid*144 + 128] = *(unsigned short*)&hh;
        binlo[tid*144 + 128] = *(unsigned short*)&ll;
    }
    cp_wait0();
    __syncthreads();

    // ---- yacc += bins @ erel_v^T  (M=64, N=64, K=144) ----
    {
        const unsigned binA  = su32(smem + OFF_SBIN)   + (wm*16 + lh*8 + l7)*288 + lq*16;
        const unsigned binAl = su32(smem + OFF_BINLO2) + (wm*16 + lh*8 + l7)*288 + lq*16;
        const unsigned evB   = su32(smem + OFF_EVHI)   + (wg*8 + lq*32 + l7)*304 + lh*16;
        const unsigned evBl  = su32(smem + OFF_EVLO)   + (wg*8 + lq*32 + l7)*304 + lh*16;
        #pragma unroll
        for (int ks = 0; ks < 9; ks++) {
            const unsigned ko = ks*32;
            unsigned aH0,aH1,aH2,aH3, aL0,aL1,aL2,aL3;
            ldsm4(aH0,aH1,aH2,aH3, binA + ko);
            ldsm4(aL0,aL1,aL2,aL3, binAl + ko);
            unsigned bH[4], bL[4];
            ldsm4(bH[0],bH[1],bH[2],bH[3], evB + ko);
            ldsm4(bL[0],bL[1],bL[2],bL[3], evBl + ko);
            #pragma unroll
            for (int ti = 0; ti < 2; ti++) {
                unsigned b0h = bH[ti*2], b1h = bH[ti*2+1];
                unsigned b0l = bL[ti*2], b1l = bL[ti*2+1];
                mma16816(yacc[ti], aH0,aH1,aH2,aH3, b0h,b1h);
                mma16816(yacc[ti], aH0,aH1,aH2,aH3, b0l,b1l);
                mma16816(yacc[ti], aL0,aL1,aL2,aL3, b0h,b1h);
            }
        }
    }

    // ---- final: y = yacc / l ; store yt bf16 hi/lo ----
    {
        const float inv0 = 1.f / sst[r0];
        const float inv1 = 1.f / sst[r1];
        const int dA = wg*8 + tg*2;
        const int dB = dA + 32;
        const int cbase = h*64;
        size_t tb0 = ((size_t)b*T_ + i0 + r0)*C_;
        size_t tb1 = ((size_t)b*T_ + i0 + r1)*C_;
        unsigned hi2, lo2;
        cv2(yacc[0][0]*inv0, yacc[0][1]*inv0, hi2, lo2);
        *(unsigned*)&g_ythi[tb0 + cbase + dA] = hi2;
        *(unsigned*)&g_ytlo[tb0 + cbase + dA] = lo2;
        cv2(yacc[0][2]*inv1, yacc[0][3]*inv1, hi2, lo2);
        *(unsigned*)&g_ythi[tb1 + cbase + dA] = hi2;
        *(unsigned*)&g_ytlo[tb1 + cbase + dA] = lo2;
        cv2(yacc[1][0]*inv0, yacc[1][1]*inv0, hi2, lo2);
        *(unsigned*)&g_ythi[tb0 + cbase + dB] = hi2;
        *(unsigned*)&g_ytlo[tb0 + cbase + dB] = lo2;
        cv2(yacc[1][2]*inv1, yacc[1][3]*inv1, hi2, lo2);
        *(unsigned*)&g_ythi[tb1 + cbase + dB] = hi2;
        *(unsigned*)&g_ytlo[tb1 + cbase + dB] = lo2;
    }
}

// =====================================================================
extern "C" void kernel_launch(void* const* d_in, const int* in_sizes, int n_in,
                              void* d_out, int out_size)
{
    const float* x     = (const float*)d_in[0];
    const float* xmask = (const float*)d_in[1];
    const float* Wq    = (const float*)d_in[2];
    const float* bq    = (const float*)d_in[3];
    const float* Wk    = (const float*)d_in[4];
    const float* bk    = (const float*)d_in[5];
    const float* Wv    = (const float*)d_in[6];
    const float* bv    = (const float*)d_in[7];
    const float* Wo    = (const float*)d_in[8];
    const float* bo    = (const float*)d_in[9];
    const float* erelk = (const float*)d_in[10];
    const float* erelv = (const float*)d_in[11];
    float* out = (float*)d_out;

    cudaFuncSetAttribute(attn_kernel,
                         cudaFuncAttributeMaxDynamicSharedMemorySize, SMEM_BYTES);
    cudaFuncSetAttribute(proj_any,
                         cudaFuncAttributeMaxDynamicSharedMemorySize, PJ2_SMEM);
    cudaFuncSetAttribute(outp_any,
                         cudaFuncAttributeMaxDynamicSharedMemorySize, PO_SMEM);

    conv_x<<<dim3(T_/32, C_/32, B_), 256>>>(x);
    conv_w<<<dim3(C_*C_/256, 4), 256>>>(Wq, Wk, Wv, Wo);
    conv_erel<<<36, 256>>>(erelk, erelv);

    proj_any<<<dim3(64, 12), 256, PJ2_SMEM>>>(bq, bk, bv);

    attn_kernel<<<dim3(16, H_, B_), 512, SMEM_BYTES>>>(xmask);

    outp_any<<<dim3(4, 32), 256, PO_SMEM>>>(bo, xmask, out);
}